// round 11
// baseline (speedup 1.0000x reference)
#include <cuda_runtime.h>
#include <math.h>
#include <stdint.h>

#define NB 4
#define KL 512
#define QL 32
#define SS 64
#define EE 512
#define HH 8
#define DD 64

// Scratch (allocation-free: __device__ globals). ALL NATURAL LAYOUTS.
__device__ float g_kproj[NB * KL * EE];        // 4 MB  (rna tf32)
__device__ float g_vT   [NB * HH * DD * KL];   // 4 MB  ([d][key], rna tf32)
__device__ float g_attn [NB * QL * SS * EE];   // 16 MB (rna tf32)
__device__ float g_WoR  [EE * EE];             // 1 MB  (rna tf32)

// ===========================================================================
// helpers
// ===========================================================================
__device__ __forceinline__ float to_tf32(float x) {
    uint32_t o;
    asm("cvt.rna.tf32.f32 %0, %1;" : "=r"(o) : "f"(x));
    return __uint_as_float(o);
}

__device__ __forceinline__ float fexp2(float x) {
    float y;
    asm("ex2.approx.ftz.f32 %0, %1;" : "=f"(y) : "f"(x));
    return y;
}

__device__ __forceinline__ uint32_t smem_u32(const void* p) {
    uint32_t a;
    asm("{ .reg .u64 t; cvta.to.shared.u64 t, %1; cvt.u32.u64 %0, t; }"
        : "=r"(a) : "l"(p));
    return a;
}

__device__ __forceinline__ void cp_async16(uint32_t dst, const void* src) {
    asm volatile("cp.async.cg.shared.global [%0], [%1], 16;"
                 :: "r"(dst), "l"(src) : "memory");
}
#define CP_COMMIT() asm volatile("cp.async.commit_group;" ::: "memory")
#define CP_WAIT0()  asm volatile("cp.async.wait_group 0;" ::: "memory")

__device__ __forceinline__ void mma_tf32(float c[4],
                                         uint32_t a0, uint32_t a1,
                                         uint32_t a2, uint32_t a3,
                                         uint32_t b0, uint32_t b1) {
    asm volatile(
        "mma.sync.aligned.m16n8k8.row.col.f32.tf32.tf32.f32 "
        "{%0,%1,%2,%3}, {%4,%5,%6,%7}, {%8,%9}, {%0,%1,%2,%3};"
        : "+f"(c[0]), "+f"(c[1]), "+f"(c[2]), "+f"(c[3])
        : "r"(a0), "r"(a1), "r"(a2), "r"(a3), "r"(b0), "r"(b1));
}

// ===========================================================================
// K/V projections on HMMA tf32 + Wo rna copy.  (unchanged from R10)
// grid = (40, HH): x<16 -> K, x<32 -> V (transposed), x>=32 -> Wo prep.
// ===========================================================================
#define PJ_S 68
#define PROJ_SMEM ((128 * PJ_S + 64 * PJ_S) * 4)

__global__ __launch_bounds__(256) void proj_all_kernel(
    const float* __restrict__ keys,   const float* __restrict__ Wk,
    const float* __restrict__ values, const float* __restrict__ Wv,
    const float* __restrict__ Wo)
{
    extern __shared__ float sm[];
    float* sIn = sm;
    float* sW  = sm + 128 * PJ_S;
    const uint32_t smb = smem_u32(sm);

    const int tid = threadIdx.x;
    const int h = blockIdx.y;
    const int bx = blockIdx.x;

    if (bx >= 32) {
        const int tg = (((bx - 32) * 8 + h) << 8) + tid;
        #pragma unroll
        for (int j = 0; j < 2; j++) {
            int gid = tg + j * 16384;
            int r = gid >> 6, grp = gid & 63;
            const float* src = Wo + (size_t)r * EE + grp * 8;
            float4 a = *(const float4*)(src);
            float4 b = *(const float4*)(src + 4);
            float* dst = g_WoR + (size_t)r * EE + grp * 8;
            *(float4*)(dst)     = make_float4(to_tf32(a.x), to_tf32(a.y),
                                              to_tf32(a.z), to_tf32(a.w));
            *(float4*)(dst + 4) = make_float4(to_tf32(b.x), to_tf32(b.y),
                                              to_tf32(b.z), to_tf32(b.w));
        }
        return;
    }

    const int w = tid >> 5, l = tid & 31;
    const int gr = l >> 2, q = l & 3;
    const int rw = w * 16;

    const int mode = (bx >= 16);
    const int row0 = (bx & 15) * 128;

    if (mode == 0) {
        #pragma unroll
        for (int j = 0; j < 8; j++) {
            int c = tid + j * 256;
            int r = c >> 4, col = (c & 15) * 4;
            cp_async16(smb + (uint32_t)(r * PJ_S + col) * 4,
                       keys + (size_t)(row0 + r) * EE + h * DD + col);
        }
        #pragma unroll
        for (int j = 0; j < 4; j++) {
            int c = tid + j * 256;
            int r = c >> 4, col = (c & 15) * 4;
            cp_async16(smb + (uint32_t)(128 * PJ_S + r * PJ_S + col) * 4,
                       Wk + (size_t)r * 64 + col);
        }
        CP_COMMIT();
        CP_WAIT0();
    } else {
        for (int i = tid; i < 2048; i += 256) {
            int r = i >> 4, c4 = i & 15;
            float4 v = *(const float4*)(values + (size_t)(row0 + r) * EE
                                        + h * DD + c4 * 4);
            v.x = to_tf32(v.x); v.y = to_tf32(v.y);
            v.z = to_tf32(v.z); v.w = to_tf32(v.w);
            *(float4*)(sIn + r * PJ_S + c4 * 4) = v;
        }
        for (int i = tid; i < 1024; i += 256) {
            int r = i >> 4, c4 = i & 15;
            float4 v = *(const float4*)(Wv + (size_t)r * 64 + c4 * 4);
            v.x = to_tf32(v.x); v.y = to_tf32(v.y);
            v.z = to_tf32(v.z); v.w = to_tf32(v.w);
            *(float4*)(sW + r * PJ_S + c4 * 4) = v;
        }
    }
    __syncthreads();

    float acc[8][4];
    #pragma unroll
    for (int nt = 0; nt < 8; nt++)
        #pragma unroll
        for (int j = 0; j < 4; j++) acc[nt][j] = 0.f;

    #pragma unroll
    for (int ks = 0; ks < 8; ks++) {
        float2 A02 = *(const float2*)(sIn + (rw + gr) * PJ_S + ks * 8 + 2 * q);
        float2 A13 = *(const float2*)(sIn + (rw + gr + 8) * PJ_S + ks * 8 + 2 * q);
        uint32_t a0 = __float_as_uint(A02.x), a2 = __float_as_uint(A02.y);
        uint32_t a1 = __float_as_uint(A13.x), a3 = __float_as_uint(A13.y);
        #pragma unroll
        for (int nt = 0; nt < 8; nt++) {
            float2 B = *(const float2*)(sW + (nt * 8 + gr) * PJ_S + ks * 8 + 2 * q);
            mma_tf32(acc[nt], a0, a1, a2, a3,
                     __float_as_uint(B.x), __float_as_uint(B.y));
        }
    }
    __syncthreads();

    if (mode == 0) {
        #pragma unroll
        for (int nt = 0; nt < 8; nt++) {
            *(float2*)(sm + (rw + gr) * PJ_S + nt * 8 + 2 * q) =
                make_float2(to_tf32(acc[nt][0]), to_tf32(acc[nt][1]));
            *(float2*)(sm + (rw + gr + 8) * PJ_S + nt * 8 + 2 * q) =
                make_float2(to_tf32(acc[nt][2]), to_tf32(acc[nt][3]));
        }
        __syncthreads();
        #pragma unroll
        for (int j = 0; j < 8; j++) {
            int i = tid + j * 256;
            int r = i >> 4, c4 = i & 15;
            *(float4*)(g_kproj + (size_t)(row0 + r) * EE + h * DD + c4 * 4) =
                *(const float4*)(sm + r * PJ_S + c4 * 4);
        }
    } else {
        const int n = row0 >> 9;
        const int keyb = row0 & (KL - 1);
        const int kA = rw + gr, kB = rw + gr + 8;
        #pragma unroll
        for (int nt = 0; nt < 8; nt++) {
            int c0 = nt * 8 + 2 * q, c1 = c0 + 1;
            sm[c0 * 132 + kA] = to_tf32(acc[nt][0]);
            sm[c1 * 132 + kA] = to_tf32(acc[nt][1]);
            sm[c0 * 132 + kB] = to_tf32(acc[nt][2]);
            sm[c1 * 132 + kB] = to_tf32(acc[nt][3]);
        }
        __syncthreads();
        float* base = g_vT + (size_t)(n * HH + h) * DD * KL + keyb;
        #pragma unroll
        for (int j = 0; j < 8; j++) {
            int i = tid + j * 256;
            int d = i >> 5, c8 = i & 31;
            *(float4*)(base + (size_t)d * KL + c8 * 4) =
                *(const float4*)(sm + d * 132 + c8 * 4);
        }
    }
}

// ===========================================================================
// Flash attention: 256 threads, 8 warps x 16 q-rows (~105 regs/thread
// -> 2 CTAs/SM -> 16 warps/SM = 4/SMSP for latency hiding).
// Fused Q-projection (cp.async raw inputs), natural layouts, float2 frags.
// ===========================================================================
#define KS_ 72
#define VS_ 72
#define QS_ 72
#define KB_OFF   0
#define VB_OFF   (2 * 64 * KS_)
#define WQ_OFF   (VB_OFF + 2 * 64 * VS_)
#define MSK_OFF  (WQ_OFF + 64 * QS_)
#define ATTN_SMEM ((MSK_OFF + 16) * 4)
#define QA_OFF   (KB_OFF + 64 * KS_)
#define QB_OFF   (VB_OFF + 64 * VS_)

__global__ __launch_bounds__(256, 2) void attn_mma_kernel(
    const float* __restrict__ query, const float* __restrict__ Wq,
    const int* __restrict__ mask)
{
    extern __shared__ float sm[];
    uint32_t* sMask = (uint32_t*)(sm + MSK_OFF);
    const uint32_t smb = smem_u32(sm);

    const int tid = threadIdx.x;
    const int w = tid >> 5, l = tid & 31;
    const int gr = l >> 2, q = l & 3;
    const int rw = w * 16;

    const int h  = blockIdx.y;
    const int bx = blockIdx.x;
    const int n  = bx >> 4;
    const size_t row0 = (size_t)bx * 128;

    const float* kbase = g_kproj + (size_t)(n * KL) * EE + h * DD;
    const float* vbase = g_vT + (size_t)(n * HH + h) * DD * KL;

    int pr[4];
    #pragma unroll
    for (int j = 0; j < 4; j++) pr[j] = (tid + j * 256) >> 4;
    const int pc = (tid & 15) * 4;

    if (tid < 16) {
        uint32_t wv = 0;
        const int* mp = mask + n * KL + tid * 32;
        #pragma unroll
        for (int b = 0; b < 32; b++) wv |= (mp[b] ? (1u << b) : 0u);
        sMask[tid] = wv;
    }

    // prologue: cp.async Q (raw), Wq (raw), K0, V0 — one group
    #pragma unroll
    for (int j = 0; j < 8; j++) {
        int c = tid + j * 256;
        int r = c >> 4, col = (c & 15) * 4;
        uint32_t dst = (r < 64) ? smb + (uint32_t)(QA_OFF + r * QS_ + col) * 4
                                : smb + (uint32_t)(QB_OFF + (r - 64) * QS_ + col) * 4;
        cp_async16(dst, query + (row0 + r) * EE + h * DD + col);
    }
    #pragma unroll
    for (int j = 0; j < 4; j++) {
        int c = tid + j * 256;
        int r = c >> 4, col = (c & 15) * 4;
        cp_async16(smb + (uint32_t)(WQ_OFF + r * QS_ + col) * 4,
                   Wq + (size_t)r * 64 + col);
    }
    {
        uint32_t kd = smb + KB_OFF * 4, vd = smb + VB_OFF * 4;
        #pragma unroll
        for (int j = 0; j < 4; j++)
            cp_async16(kd + (pr[j] * KS_ + pc) * 4, kbase + (size_t)pr[j] * EE + pc);
        #pragma unroll
        for (int j = 0; j < 4; j++)
            cp_async16(vd + (pr[j] * VS_ + pc) * 4, vbase + (size_t)pr[j] * KL + pc);
        CP_COMMIT();
    }
    CP_WAIT0();
    __syncthreads();

    // ---- fused Q projection (one 16-row strip per warp) ----
    float qa[8][4];
    {
        float qacc[8][4];
        #pragma unroll
        for (int nt = 0; nt < 8; nt++)
            #pragma unroll
            for (int j = 0; j < 4; j++) qacc[nt][j] = 0.f;

        const float* qrow = (w < 4) ? sm + QA_OFF + (rw + gr) * QS_
                                    : sm + QB_OFF + (rw + gr - 64) * QS_;
        #pragma unroll
        for (int ks = 0; ks < 8; ks++) {
            float2 A02 = *(const float2*)(qrow + ks * 8 + 2 * q);
            float2 A13 = *(const float2*)(qrow + 8 * QS_ + ks * 8 + 2 * q);
            uint32_t a0 = __float_as_uint(A02.x), a2 = __float_as_uint(A02.y);
            uint32_t a1 = __float_as_uint(A13.x), a3 = __float_as_uint(A13.y);
            #pragma unroll
            for (int nt = 0; nt < 8; nt++) {
                float2 B = *(const float2*)(sm + WQ_OFF + (nt * 8 + gr) * QS_
                                            + ks * 8 + 2 * q);
                mma_tf32(qacc[nt], a0, a1, a2, a3,
                         __float_as_uint(B.x), __float_as_uint(B.y));
            }
        }
        #pragma unroll
        for (int nt = 0; nt < 8; nt++) {
            qa[nt][0] = to_tf32(qacc[nt][0]);
            qa[nt][1] = to_tf32(qacc[nt][2]);
            qa[nt][2] = to_tf32(qacc[nt][1]);
            qa[nt][3] = to_tf32(qacc[nt][3]);
        }
    }
    __syncthreads();   // QA/QB reads done before t=0 prefetch overwrites them

    const float SC2   = 0.04419417382415922f * 1.4426950408889634f;
    const float NEGV2 = -1e20f * (0.04419417382415922f * 1.4426950408889634f);

    float o[8][4];
    #pragma unroll
    for (int nt = 0; nt < 8; nt++)
        #pragma unroll
        for (int j = 0; j < 4; j++) o[nt][j] = 0.f;
    float lp0 = 0.f, lp1 = 0.f;

    int p = 0;
    for (int t = 0; t < 8; t++) {
        if (t < 7) {
            uint32_t kd = smb + (KB_OFF + (p ^ 1) * 64 * KS_) * 4;
            uint32_t vd = smb + (VB_OFF + (p ^ 1) * 64 * VS_) * 4;
            const float* ks = kbase + (size_t)(t + 1) * 64 * EE;
            const float* vs = vbase + (t + 1) * 64;
            #pragma unroll
            for (int j = 0; j < 4; j++)
                cp_async16(kd + (pr[j] * KS_ + pc) * 4, ks + (size_t)pr[j] * EE + pc);
            #pragma unroll
            for (int j = 0; j < 4; j++)
                cp_async16(vd + (pr[j] * VS_ + pc) * 4, vs + (size_t)pr[j] * KL + pc);
            CP_COMMIT();
        }

        const float* kb = sm + KB_OFF + p * 64 * KS_;
        const float* vb = sm + VB_OFF + p * 64 * VS_;

        // ---- S = Q @ K^T ----
        float cs[8][4];
        #pragma unroll
        for (int nt = 0; nt < 8; nt++)
            #pragma unroll
            for (int j = 0; j < 4; j++) cs[nt][j] = 0.f;

        #pragma unroll
        for (int ks = 0; ks < 8; ks++) {
            uint32_t a0 = __float_as_uint(qa[ks][0]);
            uint32_t a1 = __float_as_uint(qa[ks][1]);
            uint32_t a2 = __float_as_uint(qa[ks][2]);
            uint32_t a3 = __float_as_uint(qa[ks][3]);
            #pragma unroll
            for (int nt = 0; nt < 8; nt++) {
                float2 B = *(const float2*)(kb + (nt * 8 + gr) * KS_ + ks * 8 + 2 * q);
                mma_tf32(cs[nt], a0, a1, a2, a3,
                         __float_as_uint(B.x), __float_as_uint(B.y));
            }
        }

        // ---- max-free softmax ----
        unsigned long long mm =
            (unsigned long long)sMask[t * 2] |
            ((unsigned long long)sMask[t * 2 + 1] << 32);

        #pragma unroll
        for (int nt = 0; nt < 8; nt++) {
            int c0 = nt * 8 + 2 * q, c1 = c0 + 1;
            bool k0 = (mm >> c0) & 1ull, k1 = (mm >> c1) & 1ull;
            float p0 = to_tf32(fexp2(k0 ? cs[nt][0] * SC2 : NEGV2));
            float p1 = to_tf32(fexp2(k1 ? cs[nt][1] * SC2 : NEGV2));
            float p2 = to_tf32(fexp2(k0 ? cs[nt][2] * SC2 : NEGV2));
            float p3 = to_tf32(fexp2(k1 ? cs[nt][3] * SC2 : NEGV2));
            lp0 += p0 + p1;  lp1 += p2 + p3;
            cs[nt][0] = p0; cs[nt][1] = p1; cs[nt][2] = p2; cs[nt][3] = p3;
        }

        // ---- O += P @ V ----
        #pragma unroll
        for (int ks = 0; ks < 8; ks++) {
            uint32_t a0 = __float_as_uint(cs[ks][0]);
            uint32_t a1 = __float_as_uint(cs[ks][2]);
            uint32_t a2 = __float_as_uint(cs[ks][1]);
            uint32_t a3 = __float_as_uint(cs[ks][3]);
            #pragma unroll
            for (int nt = 0; nt < 8; nt++) {
                float2 B = *(const float2*)(vb + (nt * 8 + gr) * VS_ + ks * 8 + 2 * q);
                mma_tf32(o[nt], a0, a1, a2, a3,
                         __float_as_uint(B.x), __float_as_uint(B.y));
            }
        }

        if (t < 7) {
            CP_WAIT0();
            __syncthreads();
            p ^= 1;
        }
    }

    // ---- epilogue ----
    {
        lp0 += __shfl_xor_sync(0xffffffffu, lp0, 1);
        lp0 += __shfl_xor_sync(0xffffffffu, lp0, 2);
        lp1 += __shfl_xor_sync(0xffffffffu, lp1, 1);
        lp1 += __shfl_xor_sync(0xffffffffu, lp1, 2);
        float i0 = 1.0f / lp0, i1 = 1.0f / lp1;
        float* d0 = g_attn + (row0 + rw + gr) * EE + h * DD;
        float* d1 = d0 + 8 * EE;
        #pragma unroll
        for (int nt = 0; nt < 8; nt++) {
            int c = nt * 8 + 2 * q;
            *(float2*)(d0 + c) = make_float2(to_tf32(o[nt][0] * i0),
                                             to_tf32(o[nt][1] * i0));
            *(float2*)(d1 + c) = make_float2(to_tf32(o[nt][2] * i1),
                                             to_tf32(o[nt][3] * i1));
        }
    }
}

// ===========================================================================
// Output projection: 256x128 tiles (L2 traffic 128->96MB), 256 threads,
// 8 warps x 32 rows (strips A/B). k-chunk 32, cp.async ping-pong. grid (32,4).
// ===========================================================================
#define OS 40
#define XB_OFF 0
#define WB_OFF (2 * 256 * OS)
#define OUTP_SMEM ((WB_OFF + 2 * 128 * OS) * 4)

__global__ __launch_bounds__(256, 1) void outproj_mma_kernel(
    const float* __restrict__ bo, float* __restrict__ out)
{
    extern __shared__ float sm[];
    const uint32_t smb = smem_u32(sm);

    const int tid = threadIdx.x;
    const int w = tid >> 5, l = tid & 31;
    const int gr = l >> 2, q = l & 3;
    const int rA0 = w * 32 + gr;
    const int rB0 = rA0 + 16;

    const size_t row0 = (size_t)blockIdx.x * 256;
    const int    col0 = blockIdx.y * 128;

    // X: 256 rows x 32k = 2048 chunks (8/thread); W: 128 x 32 = 1024 (4/thread)
    int xr[8];
    #pragma unroll
    for (int j = 0; j < 8; j++) xr[j] = (tid + j * 256) >> 3;
    const int cc = (tid & 7) * 4;

    float accA[16][4], accB[16][4];
    #pragma unroll
    for (int nt = 0; nt < 16; nt++)
        #pragma unroll
        for (int j = 0; j < 4; j++) { accA[nt][j] = 0.f; accB[nt][j] = 0.f; }

    {
        uint32_t xd = smb + XB_OFF * 4, wd = smb + WB_OFF * 4;
        const float* xs = g_attn + row0 * EE;
        const float* ws = g_WoR + (size_t)col0 * EE;
        #pragma unroll
        for (int j = 0; j < 8; j++)
            cp_async16(xd + (xr[j] * OS + cc) * 4, xs + (size_t)xr[j] * EE + cc);
        #pragma unroll
        for (int j = 0; j < 4; j++)
            cp_async16(wd + (xr[j] * OS + cc) * 4, ws + (size_t)xr[j] * EE + cc);
        CP_COMMIT();
        CP_WAIT0();
        __syncthreads();
    }

    int p = 0;
    for (int fc = 0; fc < 16; fc++) {
        if (fc < 15) {
            uint32_t xd = smb + (XB_OFF + (p ^ 1) * 256 * OS) * 4;
            uint32_t wd = smb + (WB_OFF + (p ^ 1) * 128 * OS) * 4;
            const float* xs = g_attn + row0 * EE + (fc + 1) * 32;
            const float* ws = g_WoR + (size_t)col0 * EE + (fc + 1) * 32;
            #pragma unroll
            for (int j = 0; j < 8; j++)
                cp_async16(xd + (xr[j] * OS + cc) * 4, xs + (size_t)xr[j] * EE + cc);
            #pragma unroll
            for (int j = 0; j < 4; j++)
                cp_async16(wd + (xr[j] * OS + cc) * 4, ws + (size_t)xr[j] * EE + cc);
            CP_COMMIT();
        }

        const float* sX = sm + XB_OFF + p * 256 * OS;
        const float* sW = sm + WB_OFF + p * 128 * OS;

        #pragma unroll
        for (int ks = 0; ks < 4; ks++) {
            float2 A02 = *(const float2*)(sX + rA0 * OS + ks * 8 + 2 * q);
            float2 A13 = *(const float2*)(sX + (rA0 + 8) * OS + ks * 8 + 2 * q);
            float2 C02 = *(const float2*)(sX + rB0 * OS + ks * 8 + 2 * q);
            float2 C13 = *(const float2*)(sX + (rB0 + 8) * OS + ks * 8 + 2 * q);
            uint32_t aa0 = __float_as_uint(A02.x), aa2 = __float_as_uint(A02.y);
            uint32_t aa1 = __float_as_uint(A13.x), aa3 = __float_as_uint(A13.y);
            uint32_t ba0 = __float_as_uint(C02.x), ba2 = __float_as_uint(C02.y);
            uint32_t ba1 = __float_as_uint(C13.x), ba3 = __float_as_uint(C13.y);
            #pragma unroll
            for (int nt = 0; nt < 16; nt++) {
                float2 B = *(const float2*)(sW + (nt * 8 + gr) * OS + ks * 8 + 2 * q);
                uint32_t b0 = __float_as_uint(B.x), b1 = __float_as_uint(B.y);
                mma_tf32(accA[nt], aa0, aa1, aa2, aa3, b0, b1);
                mma_tf32(accB[nt], ba0, ba1, ba2, ba3, b0, b1);
            }
        }

        if (fc < 15) {
            CP_WAIT0();
            __syncthreads();
            p ^= 1;
        }
    }

    float* dA0 = out + (row0 + rA0) * EE + col0;
    float* dA1 = dA0 + 8 * EE;
    float* dB0 = out + (row0 + rB0) * EE + col0;
    float* dB1 = dB0 + 8 * EE;
    #pragma unroll
    for (int nt = 0; nt < 16; nt++) {
        int c = nt * 8 + 2 * q;
        float b0 = bo[col0 + c], b1 = bo[col0 + c + 1];
        *(float2*)(dA0 + c) = make_float2(accA[nt][0] + b0, accA[nt][1] + b1);
        *(float2*)(dA1 + c) = make_float2(accA[nt][2] + b0, accA[nt][3] + b1);
        *(float2*)(dB0 + c) = make_float2(accB[nt][0] + b0, accB[nt][1] + b1);
        *(float2*)(dB1 + c) = make_float2(accB[nt][2] + b0, accB[nt][3] + b1);
    }
}

// ===========================================================================
extern "C" void kernel_launch(void* const* d_in, const int* in_sizes, int n_in,
                              void* d_out, int out_size)
{
    const float* values = (const float*)d_in[0];
    const float* keys   = (const float*)d_in[1];
    const float* query  = (const float*)d_in[2];
    const int*   mask   = (const int*)  d_in[3];
    const float* Wv     = (const float*)d_in[4];
    const float* Wk     = (const float*)d_in[5];
    const float* Wq     = (const float*)d_in[6];
    const float* Wo     = (const float*)d_in[7];
    const float* bo     = (const float*)d_in[8];
    float* out          = (float*)d_out;

    cudaFuncSetAttribute(proj_all_kernel,
                         cudaFuncAttributeMaxDynamicSharedMemorySize, PROJ_SMEM);
    cudaFuncSetAttribute(attn_mma_kernel,
                         cudaFuncAttributeMaxDynamicSharedMemorySize, ATTN_SMEM);
    cudaFuncSetAttribute(outproj_mma_kernel,
                         cudaFuncAttributeMaxDynamicSharedMemorySize, OUTP_SMEM);

    // K/V projections + Wo prep
    proj_all_kernel<<<dim3(40, HH), 256, PROJ_SMEM>>>(keys, Wk, values, Wv, Wo);

    // Flash attention with fused Q projection (8 x 16-row warps, 4 warps/SMSP)
    attn_mma_kernel<<<dim3(64, HH), 256, ATTN_SMEM>>>(query, Wq, mask);

    // Output projection + bias (256x128 tiles)
    outproj_mma_kernel<<<dim3(32, 4), 256, OUTP_SMEM>>>(bo, out);
}

// round 12
// speedup vs baseline: 1.0781x; 1.0781x over previous
#include <cuda_runtime.h>
#include <math.h>
#include <stdint.h>

#define NB 4
#define KL 512
#define QL 32
#define SS 64
#define EE 512
#define HH 8
#define DD 64

// Scratch (allocation-free: __device__ globals). ALL NATURAL LAYOUTS.
__device__ float g_kproj[NB * KL * EE];        // 4 MB  (rna tf32)
__device__ float g_vT   [NB * HH * DD * KL];   // 4 MB  ([d][key], rna tf32)
__device__ float g_attn [NB * QL * SS * EE];   // 16 MB (rna tf32)
__device__ float g_WoR  [EE * EE];             // 1 MB  (rna tf32)

// ===========================================================================
// helpers
// ===========================================================================
__device__ __forceinline__ float to_tf32(float x) {
    uint32_t o;
    asm("cvt.rna.tf32.f32 %0, %1;" : "=r"(o) : "f"(x));
    return __uint_as_float(o);
}

__device__ __forceinline__ float fexp2(float x) {
    float y;
    asm("ex2.approx.ftz.f32 %0, %1;" : "=f"(y) : "f"(x));
    return y;
}

__device__ __forceinline__ uint32_t smem_u32(const void* p) {
    uint32_t a;
    asm("{ .reg .u64 t; cvta.to.shared.u64 t, %1; cvt.u32.u64 %0, t; }"
        : "=r"(a) : "l"(p));
    return a;
}

__device__ __forceinline__ void cp_async16(uint32_t dst, const void* src) {
    asm volatile("cp.async.cg.shared.global [%0], [%1], 16;"
                 :: "r"(dst), "l"(src) : "memory");
}
#define CP_COMMIT() asm volatile("cp.async.commit_group;" ::: "memory")
#define CP_WAIT0()  asm volatile("cp.async.wait_group 0;" ::: "memory")

__device__ __forceinline__ void mma_tf32(float c[4],
                                         uint32_t a0, uint32_t a1,
                                         uint32_t a2, uint32_t a3,
                                         uint32_t b0, uint32_t b1) {
    asm volatile(
        "mma.sync.aligned.m16n8k8.row.col.f32.tf32.tf32.f32 "
        "{%0,%1,%2,%3}, {%4,%5,%6,%7}, {%8,%9}, {%0,%1,%2,%3};"
        : "+f"(c[0]), "+f"(c[1]), "+f"(c[2]), "+f"(c[3])
        : "r"(a0), "r"(a1), "r"(a2), "r"(a3), "r"(b0), "r"(b1));
}

// ===========================================================================
// K/V projections on HMMA tf32 + Wo rna copy.
// grid = (40, HH): x<16 -> K, x<32 -> V (transposed), x>=32 -> Wo prep.
// ===========================================================================
#define PJ_S 68
#define PROJ_SMEM ((128 * PJ_S + 64 * PJ_S) * 4)

__global__ __launch_bounds__(256) void proj_all_kernel(
    const float* __restrict__ keys,   const float* __restrict__ Wk,
    const float* __restrict__ values, const float* __restrict__ Wv,
    const float* __restrict__ Wo)
{
    extern __shared__ float sm[];
    float* sIn = sm;
    float* sW  = sm + 128 * PJ_S;
    const uint32_t smb = smem_u32(sm);

    const int tid = threadIdx.x;
    const int h = blockIdx.y;
    const int bx = blockIdx.x;

    if (bx >= 32) {
        const int tg = (((bx - 32) * 8 + h) << 8) + tid;
        #pragma unroll
        for (int j = 0; j < 2; j++) {
            int gid = tg + j * 16384;
            int r = gid >> 6, grp = gid & 63;
            const float* src = Wo + (size_t)r * EE + grp * 8;
            float4 a = *(const float4*)(src);
            float4 b = *(const float4*)(src + 4);
            float* dst = g_WoR + (size_t)r * EE + grp * 8;
            *(float4*)(dst)     = make_float4(to_tf32(a.x), to_tf32(a.y),
                                              to_tf32(a.z), to_tf32(a.w));
            *(float4*)(dst + 4) = make_float4(to_tf32(b.x), to_tf32(b.y),
                                              to_tf32(b.z), to_tf32(b.w));
        }
        return;
    }

    const int w = tid >> 5, l = tid & 31;
    const int gr = l >> 2, q = l & 3;
    const int rw = w * 16;

    const int mode = (bx >= 16);
    const int row0 = (bx & 15) * 128;

    if (mode == 0) {
        #pragma unroll
        for (int j = 0; j < 8; j++) {
            int c = tid + j * 256;
            int r = c >> 4, col = (c & 15) * 4;
            cp_async16(smb + (uint32_t)(r * PJ_S + col) * 4,
                       keys + (size_t)(row0 + r) * EE + h * DD + col);
        }
        #pragma unroll
        for (int j = 0; j < 4; j++) {
            int c = tid + j * 256;
            int r = c >> 4, col = (c & 15) * 4;
            cp_async16(smb + (uint32_t)(128 * PJ_S + r * PJ_S + col) * 4,
                       Wk + (size_t)r * 64 + col);
        }
        CP_COMMIT();
        CP_WAIT0();
    } else {
        for (int i = tid; i < 2048; i += 256) {
            int r = i >> 4, c4 = i & 15;
            float4 v = *(const float4*)(values + (size_t)(row0 + r) * EE
                                        + h * DD + c4 * 4);
            v.x = to_tf32(v.x); v.y = to_tf32(v.y);
            v.z = to_tf32(v.z); v.w = to_tf32(v.w);
            *(float4*)(sIn + r * PJ_S + c4 * 4) = v;
        }
        for (int i = tid; i < 1024; i += 256) {
            int r = i >> 4, c4 = i & 15;
            float4 v = *(const float4*)(Wv + (size_t)r * 64 + c4 * 4);
            v.x = to_tf32(v.x); v.y = to_tf32(v.y);
            v.z = to_tf32(v.z); v.w = to_tf32(v.w);
            *(float4*)(sW + r * PJ_S + c4 * 4) = v;
        }
    }
    __syncthreads();

    float acc[8][4];
    #pragma unroll
    for (int nt = 0; nt < 8; nt++)
        #pragma unroll
        for (int j = 0; j < 4; j++) acc[nt][j] = 0.f;

    #pragma unroll
    for (int ks = 0; ks < 8; ks++) {
        float2 A02 = *(const float2*)(sIn + (rw + gr) * PJ_S + ks * 8 + 2 * q);
        float2 A13 = *(const float2*)(sIn + (rw + gr + 8) * PJ_S + ks * 8 + 2 * q);
        uint32_t a0 = __float_as_uint(A02.x), a2 = __float_as_uint(A02.y);
        uint32_t a1 = __float_as_uint(A13.x), a3 = __float_as_uint(A13.y);
        #pragma unroll
        for (int nt = 0; nt < 8; nt++) {
            float2 B = *(const float2*)(sW + (nt * 8 + gr) * PJ_S + ks * 8 + 2 * q);
            mma_tf32(acc[nt], a0, a1, a2, a3,
                     __float_as_uint(B.x), __float_as_uint(B.y));
        }
    }
    __syncthreads();

    if (mode == 0) {
        #pragma unroll
        for (int nt = 0; nt < 8; nt++) {
            *(float2*)(sm + (rw + gr) * PJ_S + nt * 8 + 2 * q) =
                make_float2(to_tf32(acc[nt][0]), to_tf32(acc[nt][1]));
            *(float2*)(sm + (rw + gr + 8) * PJ_S + nt * 8 + 2 * q) =
                make_float2(to_tf32(acc[nt][2]), to_tf32(acc[nt][3]));
        }
        __syncthreads();
        #pragma unroll
        for (int j = 0; j < 8; j++) {
            int i = tid + j * 256;
            int r = i >> 4, c4 = i & 15;
            *(float4*)(g_kproj + (size_t)(row0 + r) * EE + h * DD + c4 * 4) =
                *(const float4*)(sm + r * PJ_S + c4 * 4);
        }
    } else {
        const int n = row0 >> 9;
        const int keyb = row0 & (KL - 1);
        const int kA = rw + gr, kB = rw + gr + 8;
        #pragma unroll
        for (int nt = 0; nt < 8; nt++) {
            int c0 = nt * 8 + 2 * q, c1 = c0 + 1;
            sm[c0 * 132 + kA] = to_tf32(acc[nt][0]);
            sm[c1 * 132 + kA] = to_tf32(acc[nt][1]);
            sm[c0 * 132 + kB] = to_tf32(acc[nt][2]);
            sm[c1 * 132 + kB] = to_tf32(acc[nt][3]);
        }
        __syncthreads();
        float* base = g_vT + (size_t)(n * HH + h) * DD * KL + keyb;
        #pragma unroll
        for (int j = 0; j < 8; j++) {
            int i = tid + j * 256;
            int d = i >> 5, c8 = i & 31;
            *(float4*)(base + (size_t)d * KL + c8 * 4) =
                *(const float4*)(sm + d * 132 + c8 * 4);
        }
    }
}

// ===========================================================================
// Flash attention (R10 shape: 4 warps x 32 q-rows, 128 threads, 2 CTAs/SM)
// + PDL: mask/Q/Wq staging and the fused Q-projection run BEFORE
// cudaGridDependencySynchronize(), overlapping the proj kernel's tail.
// ===========================================================================
#define KS_ 72
#define VS_ 72
#define QS_ 72
#define KB_OFF   0
#define VB_OFF   (2 * 64 * KS_)
#define WQ_OFF   (VB_OFF + 2 * 64 * VS_)
#define MSK_OFF  (WQ_OFF + 64 * QS_)
#define ATTN_SMEM ((MSK_OFF + 16) * 4)
#define QA_OFF   (KB_OFF + 64 * KS_)
#define QB_OFF   (VB_OFF + 64 * VS_)

__global__ __launch_bounds__(128, 2) void attn_mma_kernel(
    const float* __restrict__ query, const float* __restrict__ Wq,
    const int* __restrict__ mask)
{
    extern __shared__ float sm[];
    uint32_t* sMask = (uint32_t*)(sm + MSK_OFF);
    const uint32_t smb = smem_u32(sm);

    const int tid = threadIdx.x;
    const int w = tid >> 5, l = tid & 31;
    const int gr = l >> 2, q = l & 3;
    const int rA0 = w * 32 + gr;
    const int rB0 = rA0 + 16;

    const int h  = blockIdx.y;
    const int bx = blockIdx.x;
    const int n  = bx >> 4;
    const size_t row0 = (size_t)bx * 128;

    const float* kbase = g_kproj + (size_t)(n * KL) * EE + h * DD;
    const float* vbase = g_vT + (size_t)(n * HH + h) * DD * KL;

    int pr[8];
    #pragma unroll
    for (int j = 0; j < 8; j++) pr[j] = (tid + j * 128) >> 4;
    const int pc = (tid & 15) * 4;

    if (tid < 16) {
        uint32_t wv = 0;
        const int* mp = mask + n * KL + tid * 32;
        #pragma unroll
        for (int b = 0; b < 32; b++) wv |= (mp[b] ? (1u << b) : 0u);
        sMask[tid] = wv;
    }

    // ---- PDL pre-sync phase: Q + Wq staging (kernel inputs only) ----
    #pragma unroll
    for (int j = 0; j < 16; j++) {
        int c = tid + j * 128;
        int r = c >> 4, col = (c & 15) * 4;
        uint32_t dst = (r < 64) ? smb + (uint32_t)(QA_OFF + r * QS_ + col) * 4
                                : smb + (uint32_t)(QB_OFF + (r - 64) * QS_ + col) * 4;
        cp_async16(dst, query + (row0 + r) * EE + h * DD + col);
    }
    #pragma unroll
    for (int j = 0; j < 8; j++) {
        int c = tid + j * 128;
        int r = c >> 4, col = (c & 15) * 4;
        cp_async16(smb + (uint32_t)(WQ_OFF + r * QS_ + col) * 4,
                   Wq + (size_t)r * 64 + col);
    }
    CP_COMMIT();
    CP_WAIT0();
    __syncthreads();

    // ---- fused Q projection (both strips) — still overlapped with proj ----
    float qaA[8][4], qaB[8][4];
    {
        #pragma unroll
        for (int nt = 0; nt < 8; nt++)
            #pragma unroll
            for (int j = 0; j < 4; j++) { qaA[nt][j] = 0.f; qaB[nt][j] = 0.f; }

        const float* qrowA = (w < 2) ? sm + QA_OFF + (w * 32 + gr) * QS_
                                     : sm + QB_OFF + (w * 32 + gr - 64) * QS_;
        const float* qrowB = qrowA + 16 * QS_;
        #pragma unroll
        for (int ks = 0; ks < 8; ks++) {
            float2 A02 = *(const float2*)(qrowA + ks * 8 + 2 * q);
            float2 A13 = *(const float2*)(qrowA + 8 * QS_ + ks * 8 + 2 * q);
            float2 C02 = *(const float2*)(qrowB + ks * 8 + 2 * q);
            float2 C13 = *(const float2*)(qrowB + 8 * QS_ + ks * 8 + 2 * q);
            uint32_t aa0 = __float_as_uint(A02.x), aa2 = __float_as_uint(A02.y);
            uint32_t aa1 = __float_as_uint(A13.x), aa3 = __float_as_uint(A13.y);
            uint32_t ba0 = __float_as_uint(C02.x), ba2 = __float_as_uint(C02.y);
            uint32_t ba1 = __float_as_uint(C13.x), ba3 = __float_as_uint(C13.y);
            #pragma unroll
            for (int nt = 0; nt < 8; nt++) {
                float2 B = *(const float2*)(sm + WQ_OFF + (nt * 8 + gr) * QS_
                                            + ks * 8 + 2 * q);
                uint32_t b0 = __float_as_uint(B.x), b1 = __float_as_uint(B.y);
                mma_tf32(qaA[nt], aa0, aa1, aa2, aa3, b0, b1);
                mma_tf32(qaB[nt], ba0, ba1, ba2, ba3, b0, b1);
            }
        }
        #pragma unroll
        for (int nt = 0; nt < 8; nt++) {
            float t1;
            t1 = qaA[nt][1];
            qaA[nt][0] = to_tf32(qaA[nt][0]); qaA[nt][1] = to_tf32(qaA[nt][2]);
            qaA[nt][2] = to_tf32(t1);         qaA[nt][3] = to_tf32(qaA[nt][3]);
            t1 = qaB[nt][1];
            qaB[nt][0] = to_tf32(qaB[nt][0]); qaB[nt][1] = to_tf32(qaB[nt][2]);
            qaB[nt][2] = to_tf32(t1);         qaB[nt][3] = to_tf32(qaB[nt][3]);
        }
    }
    __syncthreads();   // all warps done reading Q regions

    // ---- wait for proj kernel's writes (g_kproj / g_vT) ----
    cudaGridDependencySynchronize();

    // ---- stream tile 0 into p=0 buffers ----
    {
        uint32_t kd = smb + KB_OFF * 4, vd = smb + VB_OFF * 4;
        #pragma unroll
        for (int j = 0; j < 8; j++)
            cp_async16(kd + (pr[j] * KS_ + pc) * 4, kbase + (size_t)pr[j] * EE + pc);
        #pragma unroll
        for (int j = 0; j < 8; j++)
            cp_async16(vd + (pr[j] * VS_ + pc) * 4, vbase + (size_t)pr[j] * KL + pc);
        CP_COMMIT();
    }
    CP_WAIT0();
    __syncthreads();

    const float SC2   = 0.04419417382415922f * 1.4426950408889634f;
    const float NEGV2 = -1e20f * (0.04419417382415922f * 1.4426950408889634f);

    float oA[8][4], oB[8][4];
    #pragma unroll
    for (int nt = 0; nt < 8; nt++)
        #pragma unroll
        for (int j = 0; j < 4; j++) { oA[nt][j] = 0.f; oB[nt][j] = 0.f; }
    float lpA0 = 0.f, lpA1 = 0.f, lpB0 = 0.f, lpB1 = 0.f;

    int p = 0;
    for (int t = 0; t < 8; t++) {
        if (t < 7) {
            uint32_t kd = smb + (KB_OFF + (p ^ 1) * 64 * KS_) * 4;
            uint32_t vd = smb + (VB_OFF + (p ^ 1) * 64 * VS_) * 4;
            const float* ks = kbase + (size_t)(t + 1) * 64 * EE;
            const float* vs = vbase + (t + 1) * 64;
            #pragma unroll
            for (int j = 0; j < 8; j++)
                cp_async16(kd + (pr[j] * KS_ + pc) * 4, ks + (size_t)pr[j] * EE + pc);
            #pragma unroll
            for (int j = 0; j < 8; j++)
                cp_async16(vd + (pr[j] * VS_ + pc) * 4, vs + (size_t)pr[j] * KL + pc);
            CP_COMMIT();
        }

        const float* kb = sm + KB_OFF + p * 64 * KS_;
        const float* vb = sm + VB_OFF + p * 64 * VS_;

        // ---- S = Q @ K^T (shared B-fragments across strips) ----
        float csA[8][4], csB[8][4];
        #pragma unroll
        for (int nt = 0; nt < 8; nt++)
            #pragma unroll
            for (int j = 0; j < 4; j++) { csA[nt][j] = 0.f; csB[nt][j] = 0.f; }

        #pragma unroll
        for (int ks = 0; ks < 8; ks++) {
            uint32_t aa0 = __float_as_uint(qaA[ks][0]);
            uint32_t aa1 = __float_as_uint(qaA[ks][1]);
            uint32_t aa2 = __float_as_uint(qaA[ks][2]);
            uint32_t aa3 = __float_as_uint(qaA[ks][3]);
            uint32_t ba0 = __float_as_uint(qaB[ks][0]);
            uint32_t ba1 = __float_as_uint(qaB[ks][1]);
            uint32_t ba2 = __float_as_uint(qaB[ks][2]);
            uint32_t ba3 = __float_as_uint(qaB[ks][3]);
            #pragma unroll
            for (int nt = 0; nt < 8; nt++) {
                float2 B = *(const float2*)(kb + (nt * 8 + gr) * KS_ + ks * 8 + 2 * q);
                uint32_t b0 = __float_as_uint(B.x), b1 = __float_as_uint(B.y);
                mma_tf32(csA[nt], aa0, aa1, aa2, aa3, b0, b1);
                mma_tf32(csB[nt], ba0, ba1, ba2, ba3, b0, b1);
            }
        }

        // ---- max-free softmax ----
        unsigned long long mm =
            (unsigned long long)sMask[t * 2] |
            ((unsigned long long)sMask[t * 2 + 1] << 32);

        #pragma unroll
        for (int nt = 0; nt < 8; nt++) {
            int c0 = nt * 8 + 2 * q, c1 = c0 + 1;
            bool k0 = (mm >> c0) & 1ull, k1 = (mm >> c1) & 1ull;
            float pa0 = to_tf32(fexp2(k0 ? csA[nt][0] * SC2 : NEGV2));
            float pa1 = to_tf32(fexp2(k1 ? csA[nt][1] * SC2 : NEGV2));
            float pa2 = to_tf32(fexp2(k0 ? csA[nt][2] * SC2 : NEGV2));
            float pa3 = to_tf32(fexp2(k1 ? csA[nt][3] * SC2 : NEGV2));
            float pb0 = to_tf32(fexp2(k0 ? csB[nt][0] * SC2 : NEGV2));
            float pb1 = to_tf32(fexp2(k1 ? csB[nt][1] * SC2 : NEGV2));
            float pb2 = to_tf32(fexp2(k0 ? csB[nt][2] * SC2 : NEGV2));
            float pb3 = to_tf32(fexp2(k1 ? csB[nt][3] * SC2 : NEGV2));
            lpA0 += pa0 + pa1;  lpA1 += pa2 + pa3;
            lpB0 += pb0 + pb1;  lpB1 += pb2 + pb3;
            csA[nt][0] = pa0; csA[nt][1] = pa1; csA[nt][2] = pa2; csA[nt][3] = pa3;
            csB[nt][0] = pb0; csB[nt][1] = pb1; csB[nt][2] = pb2; csB[nt][3] = pb3;
        }

        // ---- O += P @ V ----
        #pragma unroll
        for (int ks = 0; ks < 8; ks++) {
            uint32_t aa0 = __float_as_uint(csA[ks][0]);
            uint32_t aa1 = __float_as_uint(csA[ks][2]);
            uint32_t aa2 = __float_as_uint(csA[ks][1]);
            uint32_t aa3 = __float_as_uint(csA[ks][3]);
            uint32_t ba0 = __float_as_uint(csB[ks][0]);
            uint32_t ba1 = __float_as_uint(csB[ks][2]);
            uint32_t ba2 = __float_as_uint(csB[ks][1]);
            uint32_t ba3 = __float_as_uint(csB[ks][3]);
            #pragma unroll
            for (int nt = 0; nt < 8; nt++) {
                float2 B = *(const float2*)(vb + (nt * 8 + gr) * VS_ + ks * 8 + 2 * q);
                uint32_t b0 = __float_as_uint(B.x), b1 = __float_as_uint(B.y);
                mma_tf32(oA[nt], aa0, aa1, aa2, aa3, b0, b1);
                mma_tf32(oB[nt], ba0, ba1, ba2, ba3, b0, b1);
            }
        }

        if (t < 7) {
            CP_WAIT0();
            __syncthreads();
            p ^= 1;
        }
    }

    // ---- epilogue ----
    {
        lpA0 += __shfl_xor_sync(0xffffffffu, lpA0, 1);
        lpA0 += __shfl_xor_sync(0xffffffffu, lpA0, 2);
        lpA1 += __shfl_xor_sync(0xffffffffu, lpA1, 1);
        lpA1 += __shfl_xor_sync(0xffffffffu, lpA1, 2);
        lpB0 += __shfl_xor_sync(0xffffffffu, lpB0, 1);
        lpB0 += __shfl_xor_sync(0xffffffffu, lpB0, 2);
        lpB1 += __shfl_xor_sync(0xffffffffu, lpB1, 1);
        lpB1 += __shfl_xor_sync(0xffffffffu, lpB1, 2);
        float iA0 = 1.0f / lpA0, iA1 = 1.0f / lpA1;
        float iB0 = 1.0f / lpB0, iB1 = 1.0f / lpB1;
        float* dA0 = g_attn + (row0 + rA0) * EE + h * DD;
        float* dA1 = dA0 + 8 * EE;
        float* dB0 = g_attn + (row0 + rB0) * EE + h * DD;
        float* dB1 = dB0 + 8 * EE;
        #pragma unroll
        for (int nt = 0; nt < 8; nt++) {
            int c = nt * 8 + 2 * q;
            *(float2*)(dA0 + c) = make_float2(to_tf32(oA[nt][0] * iA0),
                                              to_tf32(oA[nt][1] * iA0));
            *(float2*)(dA1 + c) = make_float2(to_tf32(oA[nt][2] * iA1),
                                              to_tf32(oA[nt][3] * iA1));
            *(float2*)(dB0 + c) = make_float2(to_tf32(oB[nt][0] * iB0),
                                              to_tf32(oB[nt][1] * iB0));
            *(float2*)(dB1 + c) = make_float2(to_tf32(oB[nt][2] * iB1),
                                              to_tf32(oB[nt][3] * iB1));
        }
    }
}

// ===========================================================================
// Output projection (R10 shape: 4 warps x 32 rows x 128 cols, grid (64,4))
// + PDL: W staging issued before the grid-sync (depends on proj, not attn).
// ===========================================================================
#define OS 40
#define XB_OFF 0
#define WB_OFF (2 * 128 * OS)
#define OUTP_SMEM ((4 * 128 * OS) * 4)

__global__ __launch_bounds__(128, 2) void outproj_mma_kernel(
    const float* __restrict__ bo, float* __restrict__ out)
{
    extern __shared__ float sm[];
    const uint32_t smb = smem_u32(sm);

    const int tid = threadIdx.x;
    const int w = tid >> 5, l = tid & 31;
    const int gr = l >> 2, q = l & 3;
    const int rA0 = w * 32 + gr;
    const int rB0 = rA0 + 16;

    const size_t row0 = (size_t)blockIdx.x * 128;
    const int    col0 = blockIdx.y * 128;

    int cr[8];
    #pragma unroll
    for (int j = 0; j < 8; j++) cr[j] = (tid + j * 128) >> 3;
    const int cc = (tid & 7) * 4;

    float accA[16][4], accB[16][4];
    #pragma unroll
    for (int nt = 0; nt < 16; nt++)
        #pragma unroll
        for (int j = 0; j < 4; j++) { accA[nt][j] = 0.f; accB[nt][j] = 0.f; }

    // PDL pre-sync: W stage 0 (depends only on proj's g_WoR)
    {
        uint32_t wd = smb + WB_OFF * 4;
        const float* ws = g_WoR + (size_t)col0 * EE;
        #pragma unroll
        for (int j = 0; j < 8; j++)
            cp_async16(wd + (cr[j] * OS + cc) * 4, ws + (size_t)cr[j] * EE + cc);
        CP_COMMIT();
    }

    cudaGridDependencySynchronize();   // wait for attn's g_attn writes

    {
        uint32_t xd = smb + XB_OFF * 4;
        const float* xs = g_attn + row0 * EE;
        #pragma unroll
        for (int j = 0; j < 8; j++)
            cp_async16(xd + (cr[j] * OS + cc) * 4, xs + (size_t)cr[j] * EE + cc);
        CP_COMMIT();
        CP_WAIT0();
        __syncthreads();
    }

    int p = 0;
    for (int fc = 0; fc < 16; fc++) {
        if (fc < 15) {
            uint32_t xd = smb + (XB_OFF + (p ^ 1) * 128 * OS) * 4;
            uint32_t wd = smb + (WB_OFF + (p ^ 1) * 128 * OS) * 4;
            const float* xs = g_attn + row0 * EE + (fc + 1) * 32;
            const float* ws = g_WoR + (size_t)col0 * EE + (fc + 1) * 32;
            #pragma unroll
            for (int j = 0; j < 8; j++)
                cp_async16(xd + (cr[j] * OS + cc) * 4, xs + (size_t)cr[j] * EE + cc);
            #pragma unroll
            for (int j = 0; j < 8; j++)
                cp_async16(wd + (cr[j] * OS + cc) * 4, ws + (size_t)cr[j] * EE + cc);
            CP_COMMIT();
        }

        const float* sX = sm + XB_OFF + p * 128 * OS;
        const float* sW = sm + WB_OFF + p * 128 * OS;

        #pragma unroll
        for (int ks = 0; ks < 4; ks++) {
            float2 A02 = *(const float2*)(sX + rA0 * OS + ks * 8 + 2 * q);
            float2 A13 = *(const float2*)(sX + (rA0 + 8) * OS + ks * 8 + 2 * q);
            float2 C02 = *(const float2*)(sX + rB0 * OS + ks * 8 + 2 * q);
            float2 C13 = *(const float2*)(sX + (rB0 + 8) * OS + ks * 8 + 2 * q);
            uint32_t aa0 = __float_as_uint(A02.x), aa2 = __float_as_uint(A02.y);
            uint32_t aa1 = __float_as_uint(A13.x), aa3 = __float_as_uint(A13.y);
            uint32_t ba0 = __float_as_uint(C02.x), ba2 = __float_as_uint(C02.y);
            uint32_t ba1 = __float_as_uint(C13.x), ba3 = __float_as_uint(C13.y);
            #pragma unroll
            for (int nt = 0; nt < 16; nt++) {
                float2 B = *(const float2*)(sW + (nt * 8 + gr) * OS + ks * 8 + 2 * q);
                uint32_t b0 = __float_as_uint(B.x), b1 = __float_as_uint(B.y);
                mma_tf32(accA[nt], aa0, aa1, aa2, aa3, b0, b1);
                mma_tf32(accB[nt], ba0, ba1, ba2, ba3, b0, b1);
            }
        }

        if (fc < 15) {
            CP_WAIT0();
            __syncthreads();
            p ^= 1;
        }
    }

    float* dA0 = out + (row0 + rA0) * EE + col0;
    float* dA1 = dA0 + 8 * EE;
    float* dB0 = out + (row0 + rB0) * EE + col0;
    float* dB1 = dB0 + 8 * EE;
    #pragma unroll
    for (int nt = 0; nt < 16; nt++) {
        int c = nt * 8 + 2 * q;
        float b0 = bo[col0 + c], b1 = bo[col0 + c + 1];
        *(float2*)(dA0 + c) = make_float2(accA[nt][0] + b0, accA[nt][1] + b1);
        *(float2*)(dA1 + c) = make_float2(accA[nt][2] + b0, accA[nt][3] + b1);
        *(float2*)(dB0 + c) = make_float2(accB[nt][0] + b0, accB[nt][1] + b1);
        *(float2*)(dB1 + c) = make_float2(accB[nt][2] + b0, accB[nt][3] + b1);
    }
}

// ===========================================================================
extern "C" void kernel_launch(void* const* d_in, const int* in_sizes, int n_in,
                              void* d_out, int out_size)
{
    const float* values = (const float*)d_in[0];
    const float* keys   = (const float*)d_in[1];
    const float* query  = (const float*)d_in[2];
    const int*   mask   = (const int*)  d_in[3];
    const float* Wv     = (const float*)d_in[4];
    const float* Wk     = (const float*)d_in[5];
    const float* Wq     = (const float*)d_in[6];
    const float* Wo     = (const float*)d_in[7];
    const float* bo     = (const float*)d_in[8];
    float* out          = (float*)d_out;

    cudaFuncSetAttribute(proj_all_kernel,
                         cudaFuncAttributeMaxDynamicSharedMemorySize, PROJ_SMEM);
    cudaFuncSetAttribute(attn_mma_kernel,
                         cudaFuncAttributeMaxDynamicSharedMemorySize, ATTN_SMEM);
    cudaFuncSetAttribute(outproj_mma_kernel,
                         cudaFuncAttributeMaxDynamicSharedMemorySize, OUTP_SMEM);

    // K/V projections + Wo prep
    proj_all_kernel<<<dim3(40, HH), 256, PROJ_SMEM>>>(keys, Wk, values, Wv, Wo);

    // Flash attention (PDL: prologue overlaps proj tail)
    {
        cudaLaunchConfig_t cfg = {};
        cfg.gridDim = dim3(64, HH);
        cfg.blockDim = dim3(128);
        cfg.dynamicSmemBytes = ATTN_SMEM;
        cfg.stream = 0;
        cudaLaunchAttribute at[1];
        at[0].id = cudaLaunchAttributeProgrammaticStreamSerialization;
        at[0].val.programmaticStreamSerializationAllowed = 1;
        cfg.attrs = at;
        cfg.numAttrs = 1;
        cudaLaunchKernelEx(&cfg, attn_mma_kernel, query, Wq, mask);
    }

    // Output projection (PDL: W staging overlaps attn tail)
    {
        cudaLaunchConfig_t cfg = {};
        cfg.gridDim = dim3(64, 4);
        cfg.blockDim = dim3(128);
        cfg.dynamicSmemBytes = OUTP_SMEM;
        cfg.stream = 0;
        cudaLaunchAttribute at[1];
        at[0].id = cudaLaunchAttributeProgrammaticStreamSerialization;
        at[0].val.programmaticStreamSerializationAllowed = 1;
        cfg.attrs = at;
        cfg.numAttrs = 1;
        cudaLaunchKernelEx(&cfg, outproj_mma_kernel, bo, out);
    }
}

// round 13
// speedup vs baseline: 1.1018x; 1.0220x over previous
#include <cuda_runtime.h>
#include <math.h>
#include <stdint.h>

#define NB 4
#define KL 512
#define QL 32
#define SS 64
#define EE 512
#define HH 8
#define DD 64

// Scratch (allocation-free: __device__ globals). ALL NATURAL LAYOUTS.
__device__ float g_kproj[NB * KL * EE];        // 4 MB  (rna tf32)
__device__ float g_vT   [NB * HH * DD * KL];   // 4 MB  ([d][key], rna tf32)
__device__ float g_attn [NB * QL * SS * EE];   // 16 MB (rna tf32)
__device__ float g_WoR  [EE * EE];             // 1 MB  (rna tf32)

// ===========================================================================
// helpers
// ===========================================================================
__device__ __forceinline__ float to_tf32(float x) {
    uint32_t o;
    asm("cvt.rna.tf32.f32 %0, %1;" : "=r"(o) : "f"(x));
    return __uint_as_float(o);
}

__device__ __forceinline__ float fexp2(float x) {
    float y;
    asm("ex2.approx.ftz.f32 %0, %1;" : "=f"(y) : "f"(x));
    return y;
}

__device__ __forceinline__ uint32_t smem_u32(const void* p) {
    uint32_t a;
    asm("{ .reg .u64 t; cvta.to.shared.u64 t, %1; cvt.u32.u64 %0, t; }"
        : "=r"(a) : "l"(p));
    return a;
}

__device__ __forceinline__ void cp_async16(uint32_t dst, const void* src) {
    asm volatile("cp.async.cg.shared.global [%0], [%1], 16;"
                 :: "r"(dst), "l"(src) : "memory");
}
#define CP_COMMIT() asm volatile("cp.async.commit_group;" ::: "memory")
#define CP_WAIT0()  asm volatile("cp.async.wait_group 0;" ::: "memory")

__device__ __forceinline__ void mma_tf32(float c[4],
                                         uint32_t a0, uint32_t a1,
                                         uint32_t a2, uint32_t a3,
                                         uint32_t b0, uint32_t b1) {
    asm volatile(
        "mma.sync.aligned.m16n8k8.row.col.f32.tf32.tf32.f32 "
        "{%0,%1,%2,%3}, {%4,%5,%6,%7}, {%8,%9}, {%0,%1,%2,%3};"
        : "+f"(c[0]), "+f"(c[1]), "+f"(c[2]), "+f"(c[3])
        : "r"(a0), "r"(a1), "r"(a2), "r"(a3), "r"(b0), "r"(b1));
}

// ===========================================================================
// K/V projections on HMMA tf32 + Wo rna copy.  64-row tiles, 128 threads.
// grid = (72, HH): x<32 -> K, x<64 -> V (transposed), x>=64 -> Wo prep.
// ===========================================================================
#define PJ_S 68
#define PROJ_SMEM ((2 * 64 * PJ_S) * 4)

__global__ __launch_bounds__(128) void proj_all_kernel(
    const float* __restrict__ keys,   const float* __restrict__ Wk,
    const float* __restrict__ values, const float* __restrict__ Wv,
    const float* __restrict__ Wo)
{
    extern __shared__ float sm[];
    float* sIn = sm;                 // [64][PJ_S]
    float* sW  = sm + 64 * PJ_S;     // [64][PJ_S]
    const uint32_t smb = smem_u32(sm);

    cudaTriggerProgrammaticLaunchCompletion();

    const int tid = threadIdx.x;
    const int h = blockIdx.y;
    const int bx = blockIdx.x;

    if (bx >= 64) {
        // Wo prep: rna tf32, natural layout, float4 I/O. 512 8-col groups/block.
        const int baseg = ((bx - 64) * 8 + h) * 512;
        #pragma unroll
        for (int j = 0; j < 4; j++) {
            int gid = baseg + tid + j * 128;
            int r = gid >> 6, grp = gid & 63;
            const float* src = Wo + (size_t)r * EE + grp * 8;
            float4 a = *(const float4*)(src);
            float4 b = *(const float4*)(src + 4);
            float* dst = g_WoR + (size_t)r * EE + grp * 8;
            *(float4*)(dst)     = make_float4(to_tf32(a.x), to_tf32(a.y),
                                              to_tf32(a.z), to_tf32(a.w));
            *(float4*)(dst + 4) = make_float4(to_tf32(b.x), to_tf32(b.y),
                                              to_tf32(b.z), to_tf32(b.w));
        }
        return;
    }

    const int w = tid >> 5, l = tid & 31;
    const int gr = l >> 2, q = l & 3;
    const int rw = w * 16;

    const int mode = (bx >= 32);
    const int row0 = (bx & 31) * 64;

    if (mode == 0) {
        // K path: cp.async raw inputs (truncated tf32 in mma — logit path)
        #pragma unroll
        for (int j = 0; j < 8; j++) {
            int c = tid + j * 128;
            int r = c >> 4, col = (c & 15) * 4;
            cp_async16(smb + (uint32_t)(r * PJ_S + col) * 4,
                       keys + (size_t)(row0 + r) * EE + h * DD + col);
        }
        #pragma unroll
        for (int j = 0; j < 8; j++) {
            int c = tid + j * 128;
            int r = c >> 4, col = (c & 15) * 4;
            cp_async16(smb + (uint32_t)(64 * PJ_S + r * PJ_S + col) * 4,
                       Wk + (size_t)r * 64 + col);
        }
        CP_COMMIT();
        CP_WAIT0();
    } else {
        // V path: rna staging (value path — keep round-to-nearest)
        for (int i = tid; i < 1024; i += 128) {
            int r = i >> 4, c4 = i & 15;
            float4 v = *(const float4*)(values + (size_t)(row0 + r) * EE
                                        + h * DD + c4 * 4);
            v.x = to_tf32(v.x); v.y = to_tf32(v.y);
            v.z = to_tf32(v.z); v.w = to_tf32(v.w);
            *(float4*)(sIn + r * PJ_S + c4 * 4) = v;
        }
        for (int i = tid; i < 1024; i += 128) {
            int r = i >> 4, c4 = i & 15;
            float4 v = *(const float4*)(Wv + (size_t)r * 64 + c4 * 4);
            v.x = to_tf32(v.x); v.y = to_tf32(v.y);
            v.z = to_tf32(v.z); v.w = to_tf32(v.w);
            *(float4*)(sW + r * PJ_S + c4 * 4) = v;
        }
    }
    __syncthreads();

    float acc[8][4];
    #pragma unroll
    for (int nt = 0; nt < 8; nt++)
        #pragma unroll
        for (int j = 0; j < 4; j++) acc[nt][j] = 0.f;

    #pragma unroll
    for (int ks = 0; ks < 8; ks++) {
        float2 A02 = *(const float2*)(sIn + (rw + gr) * PJ_S + ks * 8 + 2 * q);
        float2 A13 = *(const float2*)(sIn + (rw + gr + 8) * PJ_S + ks * 8 + 2 * q);
        uint32_t a0 = __float_as_uint(A02.x), a2 = __float_as_uint(A02.y);
        uint32_t a1 = __float_as_uint(A13.x), a3 = __float_as_uint(A13.y);
        #pragma unroll
        for (int nt = 0; nt < 8; nt++) {
            float2 B = *(const float2*)(sW + (nt * 8 + gr) * PJ_S + ks * 8 + 2 * q);
            mma_tf32(acc[nt], a0, a1, a2, a3,
                     __float_as_uint(B.x), __float_as_uint(B.y));
        }
    }
    __syncthreads();

    if (mode == 0) {
        #pragma unroll
        for (int nt = 0; nt < 8; nt++) {
            *(float2*)(sm + (rw + gr) * PJ_S + nt * 8 + 2 * q) =
                make_float2(to_tf32(acc[nt][0]), to_tf32(acc[nt][1]));
            *(float2*)(sm + (rw + gr + 8) * PJ_S + nt * 8 + 2 * q) =
                make_float2(to_tf32(acc[nt][2]), to_tf32(acc[nt][3]));
        }
        __syncthreads();
        #pragma unroll
        for (int j = 0; j < 8; j++) {
            int i = tid + j * 128;
            int r = i >> 4, c4 = i & 15;
            *(float4*)(g_kproj + (size_t)(row0 + r) * EE + h * DD + c4 * 4) =
                *(const float4*)(sm + r * PJ_S + c4 * 4);
        }
    } else {
        // V: transpose to [d][key] via [64][132] staging (64-key chunk)
        const int n = row0 >> 9;
        const int keyb = row0 & (KL - 1);
        const int kA = rw + gr, kB = rw + gr + 8;
        #pragma unroll
        for (int nt = 0; nt < 8; nt++) {
            int c0 = nt * 8 + 2 * q, c1 = c0 + 1;
            sm[c0 * 132 + kA] = to_tf32(acc[nt][0]);
            sm[c1 * 132 + kA] = to_tf32(acc[nt][1]);
            sm[c0 * 132 + kB] = to_tf32(acc[nt][2]);
            sm[c1 * 132 + kB] = to_tf32(acc[nt][3]);
        }
        __syncthreads();
        float* base = g_vT + (size_t)(n * HH + h) * DD * KL + keyb;
        #pragma unroll
        for (int j = 0; j < 8; j++) {
            int i = tid + j * 128;
            int d = i >> 4, c4 = i & 15;
            *(float4*)(base + (size_t)d * KL + c4 * 4) =
                *(const float4*)(sm + d * 132 + c4 * 4);
        }
    }
}

// ===========================================================================
// Flash attention (4 warps x 32 q-rows, 128 threads, 2 CTAs/SM) + PDL.
// Early trigger lets outproj launch during attn; Q staging + fused Q-proj
// run before cudaGridDependencySynchronize, overlapping proj.
// ===========================================================================
#define KS_ 72
#define VS_ 72
#define QS_ 72
#define KB_OFF   0
#define VB_OFF   (2 * 64 * KS_)
#define WQ_OFF   (VB_OFF + 2 * 64 * VS_)
#define MSK_OFF  (WQ_OFF + 64 * QS_)
#define ATTN_SMEM ((MSK_OFF + 16) * 4)
#define QA_OFF   (KB_OFF + 64 * KS_)
#define QB_OFF   (VB_OFF + 64 * VS_)

__global__ __launch_bounds__(128, 2) void attn_mma_kernel(
    const float* __restrict__ query, const float* __restrict__ Wq,
    const int* __restrict__ mask)
{
    extern __shared__ float sm[];
    uint32_t* sMask = (uint32_t*)(sm + MSK_OFF);
    const uint32_t smb = smem_u32(sm);

    cudaTriggerProgrammaticLaunchCompletion();

    const int tid = threadIdx.x;
    const int w = tid >> 5, l = tid & 31;
    const int gr = l >> 2, q = l & 3;
    const int rA0 = w * 32 + gr;
    const int rB0 = rA0 + 16;

    const int h  = blockIdx.y;
    const int bx = blockIdx.x;
    const int n  = bx >> 4;
    const size_t row0 = (size_t)bx * 128;

    const float* kbase = g_kproj + (size_t)(n * KL) * EE + h * DD;
    const float* vbase = g_vT + (size_t)(n * HH + h) * DD * KL;

    int pr[8];
    #pragma unroll
    for (int j = 0; j < 8; j++) pr[j] = (tid + j * 128) >> 4;
    const int pc = (tid & 15) * 4;

    if (tid < 16) {
        uint32_t wv = 0;
        const int* mp = mask + n * KL + tid * 32;
        #pragma unroll
        for (int b = 0; b < 32; b++) wv |= (mp[b] ? (1u << b) : 0u);
        sMask[tid] = wv;
    }

    // ---- PDL pre-sync phase: Q + Wq staging (kernel inputs only) ----
    #pragma unroll
    for (int j = 0; j < 16; j++) {
        int c = tid + j * 128;
        int r = c >> 4, col = (c & 15) * 4;
        uint32_t dst = (r < 64) ? smb + (uint32_t)(QA_OFF + r * QS_ + col) * 4
                                : smb + (uint32_t)(QB_OFF + (r - 64) * QS_ + col) * 4;
        cp_async16(dst, query + (row0 + r) * EE + h * DD + col);
    }
    #pragma unroll
    for (int j = 0; j < 8; j++) {
        int c = tid + j * 128;
        int r = c >> 4, col = (c & 15) * 4;
        cp_async16(smb + (uint32_t)(WQ_OFF + r * QS_ + col) * 4,
                   Wq + (size_t)r * 64 + col);
    }
    CP_COMMIT();
    CP_WAIT0();
    __syncthreads();

    // ---- fused Q projection (both strips) — overlapped with proj ----
    float qaA[8][4], qaB[8][4];
    {
        #pragma unroll
        for (int nt = 0; nt < 8; nt++)
            #pragma unroll
            for (int j = 0; j < 4; j++) { qaA[nt][j] = 0.f; qaB[nt][j] = 0.f; }

        const float* qrowA = (w < 2) ? sm + QA_OFF + (w * 32 + gr) * QS_
                                     : sm + QB_OFF + (w * 32 + gr - 64) * QS_;
        const float* qrowB = qrowA + 16 * QS_;
        #pragma unroll
        for (int ks = 0; ks < 8; ks++) {
            float2 A02 = *(const float2*)(qrowA + ks * 8 + 2 * q);
            float2 A13 = *(const float2*)(qrowA + 8 * QS_ + ks * 8 + 2 * q);
            float2 C02 = *(const float2*)(qrowB + ks * 8 + 2 * q);
            float2 C13 = *(const float2*)(qrowB + 8 * QS_ + ks * 8 + 2 * q);
            uint32_t aa0 = __float_as_uint(A02.x), aa2 = __float_as_uint(A02.y);
            uint32_t aa1 = __float_as_uint(A13.x), aa3 = __float_as_uint(A13.y);
            uint32_t ba0 = __float_as_uint(C02.x), ba2 = __float_as_uint(C02.y);
            uint32_t ba1 = __float_as_uint(C13.x), ba3 = __float_as_uint(C13.y);
            #pragma unroll
            for (int nt = 0; nt < 8; nt++) {
                float2 B = *(const float2*)(sm + WQ_OFF + (nt * 8 + gr) * QS_
                                            + ks * 8 + 2 * q);
                uint32_t b0 = __float_as_uint(B.x), b1 = __float_as_uint(B.y);
                mma_tf32(qaA[nt], aa0, aa1, aa2, aa3, b0, b1);
                mma_tf32(qaB[nt], ba0, ba1, ba2, ba3, b0, b1);
            }
        }
        #pragma unroll
        for (int nt = 0; nt < 8; nt++) {
            float t1;
            t1 = qaA[nt][1];
            qaA[nt][0] = to_tf32(qaA[nt][0]); qaA[nt][1] = to_tf32(qaA[nt][2]);
            qaA[nt][2] = to_tf32(t1);         qaA[nt][3] = to_tf32(qaA[nt][3]);
            t1 = qaB[nt][1];
            qaB[nt][0] = to_tf32(qaB[nt][0]); qaB[nt][1] = to_tf32(qaB[nt][2]);
            qaB[nt][2] = to_tf32(t1);         qaB[nt][3] = to_tf32(qaB[nt][3]);
        }
    }
    __syncthreads();   // all warps done reading Q regions

    // ---- wait for proj kernel's writes (g_kproj / g_vT) ----
    cudaGridDependencySynchronize();

    // ---- stream tile 0 into p=0 buffers ----
    {
        uint32_t kd = smb + KB_OFF * 4, vd = smb + VB_OFF * 4;
        #pragma unroll
        for (int j = 0; j < 8; j++)
            cp_async16(kd + (pr[j] * KS_ + pc) * 4, kbase + (size_t)pr[j] * EE + pc);
        #pragma unroll
        for (int j = 0; j < 8; j++)
            cp_async16(vd + (pr[j] * VS_ + pc) * 4, vbase + (size_t)pr[j] * KL + pc);
        CP_COMMIT();
    }
    CP_WAIT0();
    __syncthreads();

    const float SC2   = 0.04419417382415922f * 1.4426950408889634f;
    const float NEGV2 = -1e20f * (0.04419417382415922f * 1.4426950408889634f);

    float oA[8][4], oB[8][4];
    #pragma unroll
    for (int nt = 0; nt < 8; nt++)
        #pragma unroll
        for (int j = 0; j < 4; j++) { oA[nt][j] = 0.f; oB[nt][j] = 0.f; }
    float lpA0 = 0.f, lpA1 = 0.f, lpB0 = 0.f, lpB1 = 0.f;

    int p = 0;
    for (int t = 0; t < 8; t++) {
        if (t < 7) {
            uint32_t kd = smb + (KB_OFF + (p ^ 1) * 64 * KS_) * 4;
            uint32_t vd = smb + (VB_OFF + (p ^ 1) * 64 * VS_) * 4;
            const float* ks = kbase + (size_t)(t + 1) * 64 * EE;
            const float* vs = vbase + (t + 1) * 64;
            #pragma unroll
            for (int j = 0; j < 8; j++)
                cp_async16(kd + (pr[j] * KS_ + pc) * 4, ks + (size_t)pr[j] * EE + pc);
            #pragma unroll
            for (int j = 0; j < 8; j++)
                cp_async16(vd + (pr[j] * VS_ + pc) * 4, vs + (size_t)pr[j] * KL + pc);
            CP_COMMIT();
        }

        const float* kb = sm + KB_OFF + p * 64 * KS_;
        const float* vb = sm + VB_OFF + p * 64 * VS_;

        // ---- S = Q @ K^T (shared B-fragments across strips) ----
        float csA[8][4], csB[8][4];
        #pragma unroll
        for (int nt = 0; nt < 8; nt++)
            #pragma unroll
            for (int j = 0; j < 4; j++) { csA[nt][j] = 0.f; csB[nt][j] = 0.f; }

        #pragma unroll
        for (int ks = 0; ks < 8; ks++) {
            uint32_t aa0 = __float_as_uint(qaA[ks][0]);
            uint32_t aa1 = __float_as_uint(qaA[ks][1]);
            uint32_t aa2 = __float_as_uint(qaA[ks][2]);
            uint32_t aa3 = __float_as_uint(qaA[ks][3]);
            uint32_t ba0 = __float_as_uint(qaB[ks][0]);
            uint32_t ba1 = __float_as_uint(qaB[ks][1]);
            uint32_t ba2 = __float_as_uint(qaB[ks][2]);
            uint32_t ba3 = __float_as_uint(qaB[ks][3]);
            #pragma unroll
            for (int nt = 0; nt < 8; nt++) {
                float2 B = *(const float2*)(kb + (nt * 8 + gr) * KS_ + ks * 8 + 2 * q);
                uint32_t b0 = __float_as_uint(B.x), b1 = __float_as_uint(B.y);
                mma_tf32(csA[nt], aa0, aa1, aa2, aa3, b0, b1);
                mma_tf32(csB[nt], ba0, ba1, ba2, ba3, b0, b1);
            }
        }

        // ---- max-free softmax ----
        unsigned long long mm =
            (unsigned long long)sMask[t * 2] |
            ((unsigned long long)sMask[t * 2 + 1] << 32);

        #pragma unroll
        for (int nt = 0; nt < 8; nt++) {
            int c0 = nt * 8 + 2 * q, c1 = c0 + 1;
            bool k0 = (mm >> c0) & 1ull, k1 = (mm >> c1) & 1ull;
            float pa0 = to_tf32(fexp2(k0 ? csA[nt][0] * SC2 : NEGV2));
            float pa1 = to_tf32(fexp2(k1 ? csA[nt][1] * SC2 : NEGV2));
            float pa2 = to_tf32(fexp2(k0 ? csA[nt][2] * SC2 : NEGV2));
            float pa3 = to_tf32(fexp2(k1 ? csA[nt][3] * SC2 : NEGV2));
            float pb0 = to_tf32(fexp2(k0 ? csB[nt][0] * SC2 : NEGV2));
            float pb1 = to_tf32(fexp2(k1 ? csB[nt][1] * SC2 : NEGV2));
            float pb2 = to_tf32(fexp2(k0 ? csB[nt][2] * SC2 : NEGV2));
            float pb3 = to_tf32(fexp2(k1 ? csB[nt][3] * SC2 : NEGV2));
            lpA0 += pa0 + pa1;  lpA1 += pa2 + pa3;
            lpB0 += pb0 + pb1;  lpB1 += pb2 + pb3;
            csA[nt][0] = pa0; csA[nt][1] = pa1; csA[nt][2] = pa2; csA[nt][3] = pa3;
            csB[nt][0] = pb0; csB[nt][1] = pb1; csB[nt][2] = pb2; csB[nt][3] = pb3;
        }

        // ---- O += P @ V ----
        #pragma unroll
        for (int ks = 0; ks < 8; ks++) {
            uint32_t aa0 = __float_as_uint(csA[ks][0]);
            uint32_t aa1 = __float_as_uint(csA[ks][2]);
            uint32_t aa2 = __float_as_uint(csA[ks][1]);
            uint32_t aa3 = __float_as_uint(csA[ks][3]);
            uint32_t ba0 = __float_as_uint(csB[ks][0]);
            uint32_t ba1 = __float_as_uint(csB[ks][2]);
            uint32_t ba2 = __float_as_uint(csB[ks][1]);
            uint32_t ba3 = __float_as_uint(csB[ks][3]);
            #pragma unroll
            for (int nt = 0; nt < 8; nt++) {
                float2 B = *(const float2*)(vb + (nt * 8 + gr) * VS_ + ks * 8 + 2 * q);
                uint32_t b0 = __float_as_uint(B.x), b1 = __float_as_uint(B.y);
                mma_tf32(oA[nt], aa0, aa1, aa2, aa3, b0, b1);
                mma_tf32(oB[nt], ba0, ba1, ba2, ba3, b0, b1);
            }
        }

        if (t < 7) {
            CP_WAIT0();
            __syncthreads();
            p ^= 1;
        }
    }

    // ---- epilogue ----
    {
        lpA0 += __shfl_xor_sync(0xffffffffu, lpA0, 1);
        lpA0 += __shfl_xor_sync(0xffffffffu, lpA0, 2);
        lpA1 += __shfl_xor_sync(0xffffffffu, lpA1, 1);
        lpA1 += __shfl_xor_sync(0xffffffffu, lpA1, 2);
        lpB0 += __shfl_xor_sync(0xffffffffu, lpB0, 1);
        lpB0 += __shfl_xor_sync(0xffffffffu, lpB0, 2);
        lpB1 += __shfl_xor_sync(0xffffffffu, lpB1, 1);
        lpB1 += __shfl_xor_sync(0xffffffffu, lpB1, 2);
        float iA0 = 1.0f / lpA0, iA1 = 1.0f / lpA1;
        float iB0 = 1.0f / lpB0, iB1 = 1.0f / lpB1;
        float* dA0 = g_attn + (row0 + rA0) * EE + h * DD;
        float* dA1 = dA0 + 8 * EE;
        float* dB0 = g_attn + (row0 + rB0) * EE + h * DD;
        float* dB1 = dB0 + 8 * EE;
        #pragma unroll
        for (int nt = 0; nt < 8; nt++) {
            int c = nt * 8 + 2 * q;
            *(float2*)(dA0 + c) = make_float2(to_tf32(oA[nt][0] * iA0),
                                              to_tf32(oA[nt][1] * iA0));
            *(float2*)(dA1 + c) = make_float2(to_tf32(oA[nt][2] * iA1),
                                              to_tf32(oA[nt][3] * iA1));
            *(float2*)(dB0 + c) = make_float2(to_tf32(oB[nt][0] * iB0),
                                              to_tf32(oB[nt][1] * iB0));
            *(float2*)(dB1 + c) = make_float2(to_tf32(oB[nt][2] * iB1),
                                              to_tf32(oB[nt][3] * iB1));
        }
    }
}

// ===========================================================================
// Output projection (4 warps x 32 rows x 128 cols, grid (64,4)) + PDL.
// W staging issued before the grid-sync (depends on proj, not attn).
// ===========================================================================
#define OS 40
#define XB_OFF 0
#define WB_OFF (2 * 128 * OS)
#define OUTP_SMEM ((4 * 128 * OS) * 4)

__global__ __launch_bounds__(128, 2) void outproj_mma_kernel(
    const float* __restrict__ bo, float* __restrict__ out)
{
    extern __shared__ float sm[];
    const uint32_t smb = smem_u32(sm);

    const int tid = threadIdx.x;
    const int w = tid >> 5, l = tid & 31;
    const int gr = l >> 2, q = l & 3;
    const int rA0 = w * 32 + gr;
    const int rB0 = rA0 + 16;

    const size_t row0 = (size_t)blockIdx.x * 128;
    const int    col0 = blockIdx.y * 128;

    int cr[8];
    #pragma unroll
    for (int j = 0; j < 8; j++) cr[j] = (tid + j * 128) >> 3;
    const int cc = (tid & 7) * 4;

    float accA[16][4], accB[16][4];
    #pragma unroll
    for (int nt = 0; nt < 16; nt++)
        #pragma unroll
        for (int j = 0; j < 4; j++) { accA[nt][j] = 0.f; accB[nt][j] = 0.f; }

    // PDL pre-sync: W stage 0 (depends only on proj's g_WoR)
    {
        uint32_t wd = smb + WB_OFF * 4;
        const float* ws = g_WoR + (size_t)col0 * EE;
        #pragma unroll
        for (int j = 0; j < 8; j++)
            cp_async16(wd + (cr[j] * OS + cc) * 4, ws + (size_t)cr[j] * EE + cc);
        CP_COMMIT();
    }

    cudaGridDependencySynchronize();   // wait for attn's g_attn writes

    {
        uint32_t xd = smb + XB_OFF * 4;
        const float* xs = g_attn + row0 * EE;
        #pragma unroll
        for (int j = 0; j < 8; j++)
            cp_async16(xd + (cr[j] * OS + cc) * 4, xs + (size_t)cr[j] * EE + cc);
        CP_COMMIT();
        CP_WAIT0();
        __syncthreads();
    }

    int p = 0;
    for (int fc = 0; fc < 16; fc++) {
        if (fc < 15) {
            uint32_t xd = smb + (XB_OFF + (p ^ 1) * 128 * OS) * 4;
            uint32_t wd = smb + (WB_OFF + (p ^ 1) * 128 * OS) * 4;
            const float* xs = g_attn + row0 * EE + (fc + 1) * 32;
            const float* ws = g_WoR + (size_t)col0 * EE + (fc + 1) * 32;
            #pragma unroll
            for (int j = 0; j < 8; j++)
                cp_async16(xd + (cr[j] * OS + cc) * 4, xs + (size_t)cr[j] * EE + cc);
            #pragma unroll
            for (int j = 0; j < 8; j++)
                cp_async16(wd + (cr[j] * OS + cc) * 4, ws + (size_t)cr[j] * EE + cc);
            CP_COMMIT();
        }

        const float* sX = sm + XB_OFF + p * 128 * OS;
        const float* sW = sm + WB_OFF + p * 128 * OS;

        #pragma unroll
        for (int ks = 0; ks < 4; ks++) {
            float2 A02 = *(const float2*)(sX + rA0 * OS + ks * 8 + 2 * q);
            float2 A13 = *(const float2*)(sX + (rA0 + 8) * OS + ks * 8 + 2 * q);
            float2 C02 = *(const float2*)(sX + rB0 * OS + ks * 8 + 2 * q);
            float2 C13 = *(const float2*)(sX + (rB0 + 8) * OS + ks * 8 + 2 * q);
            uint32_t aa0 = __float_as_uint(A02.x), aa2 = __float_as_uint(A02.y);
            uint32_t aa1 = __float_as_uint(A13.x), aa3 = __float_as_uint(A13.y);
            uint32_t ba0 = __float_as_uint(C02.x), ba2 = __float_as_uint(C02.y);
            uint32_t ba1 = __float_as_uint(C13.x), ba3 = __float_as_uint(C13.y);
            #pragma unroll
            for (int nt = 0; nt < 16; nt++) {
                float2 B = *(const float2*)(sW + (nt * 8 + gr) * OS + ks * 8 + 2 * q);
                uint32_t b0 = __float_as_uint(B.x), b1 = __float_as_uint(B.y);
                mma_tf32(accA[nt], aa0, aa1, aa2, aa3, b0, b1);
                mma_tf32(accB[nt], ba0, ba1, ba2, ba3, b0, b1);
            }
        }

        if (fc < 15) {
            CP_WAIT0();
            __syncthreads();
            p ^= 1;
        }
    }

    float* dA0 = out + (row0 + rA0) * EE + col0;
    float* dA1 = dA0 + 8 * EE;
    float* dB0 = out + (row0 + rB0) * EE + col0;
    float* dB1 = dB0 + 8 * EE;
    #pragma unroll
    for (int nt = 0; nt < 16; nt++) {
        int c = nt * 8 + 2 * q;
        float b0 = bo[col0 + c], b1 = bo[col0 + c + 1];
        *(float2*)(dA0 + c) = make_float2(accA[nt][0] + b0, accA[nt][1] + b1);
        *(float2*)(dA1 + c) = make_float2(accA[nt][2] + b0, accA[nt][3] + b1);
        *(float2*)(dB0 + c) = make_float2(accB[nt][0] + b0, accB[nt][1] + b1);
        *(float2*)(dB1 + c) = make_float2(accB[nt][2] + b0, accB[nt][3] + b1);
    }
}

// ===========================================================================
extern "C" void kernel_launch(void* const* d_in, const int* in_sizes, int n_in,
                              void* d_out, int out_size)
{
    const float* values = (const float*)d_in[0];
    const float* keys   = (const float*)d_in[1];
    const float* query  = (const float*)d_in[2];
    const int*   mask   = (const int*)  d_in[3];
    const float* Wv     = (const float*)d_in[4];
    const float* Wk     = (const float*)d_in[5];
    const float* Wq     = (const float*)d_in[6];
    const float* Wo     = (const float*)d_in[7];
    const float* bo     = (const float*)d_in[8];
    float* out          = (float*)d_out;

    cudaFuncSetAttribute(proj_all_kernel,
                         cudaFuncAttributeMaxDynamicSharedMemorySize, PROJ_SMEM);
    cudaFuncSetAttribute(attn_mma_kernel,
                         cudaFuncAttributeMaxDynamicSharedMemorySize, ATTN_SMEM);
    cudaFuncSetAttribute(outproj_mma_kernel,
                         cudaFuncAttributeMaxDynamicSharedMemorySize, OUTP_SMEM);

    // K/V projections + Wo prep (64-row tiles, 576 short CTAs)
    proj_all_kernel<<<dim3(72, HH), 128, PROJ_SMEM>>>(keys, Wk, values, Wv, Wo);

    // Flash attention (PDL; prologue overlaps proj; early trigger for outproj)
    {
        cudaLaunchConfig_t cfg = {};
        cfg.gridDim = dim3(64, HH);
        cfg.blockDim = dim3(128);
        cfg.dynamicSmemBytes = ATTN_SMEM;
        cfg.stream = 0;
        cudaLaunchAttribute at[1];
        at[0].id = cudaLaunchAttributeProgrammaticStreamSerialization;
        at[0].val.programmaticStreamSerializationAllowed = 1;
        cfg.attrs = at;
        cfg.numAttrs = 1;
        cudaLaunchKernelEx(&cfg, attn_mma_kernel, query, Wq, mask);
    }

    // Output projection (PDL: W staging overlaps attn tail)
    {
        cudaLaunchConfig_t cfg = {};
        cfg.gridDim = dim3(64, 4);
        cfg.blockDim = dim3(128);
        cfg.dynamicSmemBytes = OUTP_SMEM;
        cfg.stream = 0;
        cudaLaunchAttribute at[1];
        at[0].id = cudaLaunchAttributeProgrammaticStreamSerialization;
        at[0].val.programmaticStreamSerializationAllowed = 1;
        cfg.attrs = at;
        cfg.numAttrs = 1;
        cudaLaunchKernelEx(&cfg, outproj_mma_kernel, bo, out);
    }
}

// round 14
// speedup vs baseline: 1.1276x; 1.0235x over previous
#include <cuda_runtime.h>
#include <math.h>
#include <stdint.h>

#define NB 4
#define KL 512
#define QL 32
#define SS 64
#define EE 512
#define HH 8
#define DD 64

// Scratch (allocation-free: __device__ globals). ALL NATURAL LAYOUTS.
__device__ float g_kproj[NB * KL * EE];        // 4 MB  (rna tf32)
__device__ float g_vT   [NB * HH * DD * KL];   // 4 MB  ([d][key], rna tf32)
__device__ float g_attn [NB * QL * SS * EE];   // 16 MB (rna tf32)
__device__ float g_WoR  [EE * EE];             // 1 MB  (rna tf32)

// ===========================================================================
// helpers
// ===========================================================================
__device__ __forceinline__ float to_tf32(float x) {
    uint32_t o;
    asm("cvt.rna.tf32.f32 %0, %1;" : "=r"(o) : "f"(x));
    return __uint_as_float(o);
}

// truncation to tf32 bits — matches what HMMA actually reads from a raw fp32
__device__ __forceinline__ float tr13(float x) {
    return __uint_as_float(__float_as_uint(x) & 0xffffe000u);
}

__device__ __forceinline__ float fexp2(float x) {
    float y;
    asm("ex2.approx.ftz.f32 %0, %1;" : "=f"(y) : "f"(x));
    return y;
}

__device__ __forceinline__ uint32_t smem_u32(const void* p) {
    uint32_t a;
    asm("{ .reg .u64 t; cvta.to.shared.u64 t, %1; cvt.u32.u64 %0, t; }"
        : "=r"(a) : "l"(p));
    return a;
}

__device__ __forceinline__ void cp_async16(uint32_t dst, const void* src) {
    asm volatile("cp.async.cg.shared.global [%0], [%1], 16;"
                 :: "r"(dst), "l"(src) : "memory");
}
#define CP_COMMIT() asm volatile("cp.async.commit_group;" ::: "memory")
#define CP_WAIT0()  asm volatile("cp.async.wait_group 0;" ::: "memory")

__device__ __forceinline__ void mma_tf32(float c[4],
                                         uint32_t a0, uint32_t a1,
                                         uint32_t a2, uint32_t a3,
                                         uint32_t b0, uint32_t b1) {
    asm volatile(
        "mma.sync.aligned.m16n8k8.row.col.f32.tf32.tf32.f32 "
        "{%0,%1,%2,%3}, {%4,%5,%6,%7}, {%8,%9}, {%0,%1,%2,%3};"
        : "+f"(c[0]), "+f"(c[1]), "+f"(c[2]), "+f"(c[3])
        : "r"(a0), "r"(a1), "r"(a2), "r"(a3), "r"(b0), "r"(b1));
}

// ===========================================================================
// K/V projections on HMMA tf32 + Wo rna copy.  64-row tiles, 128 threads.
// Both K and V paths stage raw inputs via cp.async (mma truncates to tf32).
// grid = (72, HH): x<32 -> K, x<64 -> V (transposed out), x>=64 -> Wo prep.
// ===========================================================================
#define PJ_S 68
#define PROJ_SMEM ((2 * 64 * PJ_S) * 4)

__global__ __launch_bounds__(128) void proj_all_kernel(
    const float* __restrict__ keys,   const float* __restrict__ Wk,
    const float* __restrict__ values, const float* __restrict__ Wv,
    const float* __restrict__ Wo)
{
    extern __shared__ float sm[];
    const uint32_t smb = smem_u32(sm);

    cudaTriggerProgrammaticLaunchCompletion();

    const int tid = threadIdx.x;
    const int h = blockIdx.y;
    const int bx = blockIdx.x;

    if (bx >= 64) {
        // Wo prep: rna tf32, natural layout, float4 I/O
        const int baseg = ((bx - 64) * 8 + h) * 512;
        #pragma unroll
        for (int j = 0; j < 4; j++) {
            int gid = baseg + tid + j * 128;
            int r = gid >> 6, grp = gid & 63;
            const float* src = Wo + (size_t)r * EE + grp * 8;
            float4 a = *(const float4*)(src);
            float4 b = *(const float4*)(src + 4);
            float* dst = g_WoR + (size_t)r * EE + grp * 8;
            *(float4*)(dst)     = make_float4(to_tf32(a.x), to_tf32(a.y),
                                              to_tf32(a.z), to_tf32(a.w));
            *(float4*)(dst + 4) = make_float4(to_tf32(b.x), to_tf32(b.y),
                                              to_tf32(b.z), to_tf32(b.w));
        }
        return;
    }

    const int w = tid >> 5, l = tid & 31;
    const int gr = l >> 2, q = l & 3;
    const int rw = w * 16;

    const int mode = (bx >= 32);
    const float* in = mode ? values : keys;
    const float* W  = mode ? Wv : Wk;
    const int row0 = (bx & 31) * 64;

    // cp.async raw inputs (truncated tf32 in mma)
    #pragma unroll
    for (int j = 0; j < 8; j++) {
        int c = tid + j * 128;
        int r = c >> 4, col = (c & 15) * 4;
        cp_async16(smb + (uint32_t)(r * PJ_S + col) * 4,
                   in + (size_t)(row0 + r) * EE + h * DD + col);
    }
    #pragma unroll
    for (int j = 0; j < 8; j++) {
        int c = tid + j * 128;
        int r = c >> 4, col = (c & 15) * 4;
        cp_async16(smb + (uint32_t)(64 * PJ_S + r * PJ_S + col) * 4,
                   W + (size_t)r * 64 + col);
    }
    CP_COMMIT();
    CP_WAIT0();
    __syncthreads();

    const float* sIn = sm;
    const float* sW  = sm + 64 * PJ_S;

    float acc[8][4];
    #pragma unroll
    for (int nt = 0; nt < 8; nt++)
        #pragma unroll
        for (int j = 0; j < 4; j++) acc[nt][j] = 0.f;

    #pragma unroll
    for (int ks = 0; ks < 8; ks++) {
        float2 A02 = *(const float2*)(sIn + (rw + gr) * PJ_S + ks * 8 + 2 * q);
        float2 A13 = *(const float2*)(sIn + (rw + gr + 8) * PJ_S + ks * 8 + 2 * q);
        uint32_t a0 = __float_as_uint(A02.x), a2 = __float_as_uint(A02.y);
        uint32_t a1 = __float_as_uint(A13.x), a3 = __float_as_uint(A13.y);
        #pragma unroll
        for (int nt = 0; nt < 8; nt++) {
            float2 B = *(const float2*)(sW + (nt * 8 + gr) * PJ_S + ks * 8 + 2 * q);
            mma_tf32(acc[nt], a0, a1, a2, a3,
                     __float_as_uint(B.x), __float_as_uint(B.y));
        }
    }
    __syncthreads();

    if (mode == 0) {
        #pragma unroll
        for (int nt = 0; nt < 8; nt++) {
            *(float2*)(sm + (rw + gr) * PJ_S + nt * 8 + 2 * q) =
                make_float2(to_tf32(acc[nt][0]), to_tf32(acc[nt][1]));
            *(float2*)(sm + (rw + gr + 8) * PJ_S + nt * 8 + 2 * q) =
                make_float2(to_tf32(acc[nt][2]), to_tf32(acc[nt][3]));
        }
        __syncthreads();
        #pragma unroll
        for (int j = 0; j < 8; j++) {
            int i = tid + j * 128;
            int r = i >> 4, c4 = i & 15;
            *(float4*)(g_kproj + (size_t)(row0 + r) * EE + h * DD + c4 * 4) =
                *(const float4*)(sm + r * PJ_S + c4 * 4);
        }
    } else {
        // V: transpose to [d][key] via [64][132] staging (64-key chunk)
        const int n = row0 >> 9;
        const int keyb = row0 & (KL - 1);
        const int kA = rw + gr, kB = rw + gr + 8;
        #pragma unroll
        for (int nt = 0; nt < 8; nt++) {
            int c0 = nt * 8 + 2 * q, c1 = c0 + 1;
            sm[c0 * 132 + kA] = to_tf32(acc[nt][0]);
            sm[c1 * 132 + kA] = to_tf32(acc[nt][1]);
            sm[c0 * 132 + kB] = to_tf32(acc[nt][2]);
            sm[c1 * 132 + kB] = to_tf32(acc[nt][3]);
        }
        __syncthreads();
        float* base = g_vT + (size_t)(n * HH + h) * DD * KL + keyb;
        #pragma unroll
        for (int j = 0; j < 8; j++) {
            int i = tid + j * 128;
            int d = i >> 4, c4 = i & 15;
            *(float4*)(base + (size_t)d * KL + c4 * 4) =
                *(const float4*)(sm + d * 132 + c4 * 4);
        }
    }
}

// ===========================================================================
// Flash attention (4 warps x 32 q-rows, 128 threads, 2 CTAs/SM) + PDL.
// P stays RAW in registers (mma truncates); l sums the truncated values.
// ===========================================================================
#define KS_ 72
#define VS_ 72
#define QS_ 72
#define KB_OFF   0
#define VB_OFF   (2 * 64 * KS_)
#define WQ_OFF   (VB_OFF + 2 * 64 * VS_)
#define MSK_OFF  (WQ_OFF + 64 * QS_)
#define ATTN_SMEM ((MSK_OFF + 16) * 4)
#define QA_OFF   (KB_OFF + 64 * KS_)
#define QB_OFF   (VB_OFF + 64 * VS_)

__global__ __launch_bounds__(128, 2) void attn_mma_kernel(
    const float* __restrict__ query, const float* __restrict__ Wq,
    const int* __restrict__ mask)
{
    extern __shared__ float sm[];
    uint32_t* sMask = (uint32_t*)(sm + MSK_OFF);
    const uint32_t smb = smem_u32(sm);

    cudaTriggerProgrammaticLaunchCompletion();

    const int tid = threadIdx.x;
    const int w = tid >> 5, l = tid & 31;
    const int gr = l >> 2, q = l & 3;
    const int rA0 = w * 32 + gr;
    const int rB0 = rA0 + 16;

    const int h  = blockIdx.y;
    const int bx = blockIdx.x;
    const int n  = bx >> 4;
    const size_t row0 = (size_t)bx * 128;

    const float* kbase = g_kproj + (size_t)(n * KL) * EE + h * DD;
    const float* vbase = g_vT + (size_t)(n * HH + h) * DD * KL;

    int pr[8];
    #pragma unroll
    for (int j = 0; j < 8; j++) pr[j] = (tid + j * 128) >> 4;
    const int pc = (tid & 15) * 4;

    if (tid < 16) {
        uint32_t wv = 0;
        const int* mp = mask + n * KL + tid * 32;
        #pragma unroll
        for (int b = 0; b < 32; b++) wv |= (mp[b] ? (1u << b) : 0u);
        sMask[tid] = wv;
    }

    // ---- PDL pre-sync phase: Q + Wq staging (kernel inputs only) ----
    #pragma unroll
    for (int j = 0; j < 16; j++) {
        int c = tid + j * 128;
        int r = c >> 4, col = (c & 15) * 4;
        uint32_t dst = (r < 64) ? smb + (uint32_t)(QA_OFF + r * QS_ + col) * 4
                                : smb + (uint32_t)(QB_OFF + (r - 64) * QS_ + col) * 4;
        cp_async16(dst, query + (row0 + r) * EE + h * DD + col);
    }
    #pragma unroll
    for (int j = 0; j < 8; j++) {
        int c = tid + j * 128;
        int r = c >> 4, col = (c & 15) * 4;
        cp_async16(smb + (uint32_t)(WQ_OFF + r * QS_ + col) * 4,
                   Wq + (size_t)r * 64 + col);
    }
    CP_COMMIT();
    CP_WAIT0();
    __syncthreads();

    // ---- fused Q projection (both strips) — overlapped with proj ----
    float qaA[8][4], qaB[8][4];
    {
        #pragma unroll
        for (int nt = 0; nt < 8; nt++)
            #pragma unroll
            for (int j = 0; j < 4; j++) { qaA[nt][j] = 0.f; qaB[nt][j] = 0.f; }

        const float* qrowA = (w < 2) ? sm + QA_OFF + (w * 32 + gr) * QS_
                                     : sm + QB_OFF + (w * 32 + gr - 64) * QS_;
        const float* qrowB = qrowA + 16 * QS_;
        #pragma unroll
        for (int ks = 0; ks < 8; ks++) {
            float2 A02 = *(const float2*)(qrowA + ks * 8 + 2 * q);
            float2 A13 = *(const float2*)(qrowA + 8 * QS_ + ks * 8 + 2 * q);
            float2 C02 = *(const float2*)(qrowB + ks * 8 + 2 * q);
            float2 C13 = *(const float2*)(qrowB + 8 * QS_ + ks * 8 + 2 * q);
            uint32_t aa0 = __float_as_uint(A02.x), aa2 = __float_as_uint(A02.y);
            uint32_t aa1 = __float_as_uint(A13.x), aa3 = __float_as_uint(A13.y);
            uint32_t ba0 = __float_as_uint(C02.x), ba2 = __float_as_uint(C02.y);
            uint32_t ba1 = __float_as_uint(C13.x), ba3 = __float_as_uint(C13.y);
            #pragma unroll
            for (int nt = 0; nt < 8; nt++) {
                float2 B = *(const float2*)(sm + WQ_OFF + (nt * 8 + gr) * QS_
                                            + ks * 8 + 2 * q);
                uint32_t b0 = __float_as_uint(B.x), b1 = __float_as_uint(B.y);
                mma_tf32(qaA[nt], aa0, aa1, aa2, aa3, b0, b1);
                mma_tf32(qaB[nt], ba0, ba1, ba2, ba3, b0, b1);
            }
        }
        // C-frag -> A-frag (swap [1]/[2]); raw values (mma truncates)
        #pragma unroll
        for (int nt = 0; nt < 8; nt++) {
            float t1;
            t1 = qaA[nt][1]; qaA[nt][1] = qaA[nt][2]; qaA[nt][2] = t1;
            t1 = qaB[nt][1]; qaB[nt][1] = qaB[nt][2]; qaB[nt][2] = t1;
        }
    }
    __syncthreads();   // all warps done reading Q regions

    // ---- wait for proj kernel's writes (g_kproj / g_vT) ----
    cudaGridDependencySynchronize();

    // ---- stream tile 0 into p=0 buffers ----
    {
        uint32_t kd = smb + KB_OFF * 4, vd = smb + VB_OFF * 4;
        #pragma unroll
        for (int j = 0; j < 8; j++)
            cp_async16(kd + (pr[j] * KS_ + pc) * 4, kbase + (size_t)pr[j] * EE + pc);
        #pragma unroll
        for (int j = 0; j < 8; j++)
            cp_async16(vd + (pr[j] * VS_ + pc) * 4, vbase + (size_t)pr[j] * KL + pc);
        CP_COMMIT();
    }
    CP_WAIT0();
    __syncthreads();

    const float SC2   = 0.04419417382415922f * 1.4426950408889634f;
    const float NEGV2 = -1e20f * (0.04419417382415922f * 1.4426950408889634f);

    float oA[8][4], oB[8][4];
    #pragma unroll
    for (int nt = 0; nt < 8; nt++)
        #pragma unroll
        for (int j = 0; j < 4; j++) { oA[nt][j] = 0.f; oB[nt][j] = 0.f; }
    float lpA0 = 0.f, lpA1 = 0.f, lpB0 = 0.f, lpB1 = 0.f;

    int p = 0;
    for (int t = 0; t < 8; t++) {
        if (t < 7) {
            uint32_t kd = smb + (KB_OFF + (p ^ 1) * 64 * KS_) * 4;
            uint32_t vd = smb + (VB_OFF + (p ^ 1) * 64 * VS_) * 4;
            const float* ks = kbase + (size_t)(t + 1) * 64 * EE;
            const float* vs = vbase + (t + 1) * 64;
            #pragma unroll
            for (int j = 0; j < 8; j++)
                cp_async16(kd + (pr[j] * KS_ + pc) * 4, ks + (size_t)pr[j] * EE + pc);
            #pragma unroll
            for (int j = 0; j < 8; j++)
                cp_async16(vd + (pr[j] * VS_ + pc) * 4, vs + (size_t)pr[j] * KL + pc);
            CP_COMMIT();
        }

        const float* kb = sm + KB_OFF + p * 64 * KS_;
        const float* vb = sm + VB_OFF + p * 64 * VS_;

        // ---- S = Q @ K^T (shared B-fragments across strips) ----
        float csA[8][4], csB[8][4];
        #pragma unroll
        for (int nt = 0; nt < 8; nt++)
            #pragma unroll
            for (int j = 0; j < 4; j++) { csA[nt][j] = 0.f; csB[nt][j] = 0.f; }

        #pragma unroll
        for (int ks = 0; ks < 8; ks++) {
            uint32_t aa0 = __float_as_uint(qaA[ks][0]);
            uint32_t aa1 = __float_as_uint(qaA[ks][1]);
            uint32_t aa2 = __float_as_uint(qaA[ks][2]);
            uint32_t aa3 = __float_as_uint(qaA[ks][3]);
            uint32_t ba0 = __float_as_uint(qaB[ks][0]);
            uint32_t ba1 = __float_as_uint(qaB[ks][1]);
            uint32_t ba2 = __float_as_uint(qaB[ks][2]);
            uint32_t ba3 = __float_as_uint(qaB[ks][3]);
            #pragma unroll
            for (int nt = 0; nt < 8; nt++) {
                float2 B = *(const float2*)(kb + (nt * 8 + gr) * KS_ + ks * 8 + 2 * q);
                uint32_t b0 = __float_as_uint(B.x), b1 = __float_as_uint(B.y);
                mma_tf32(csA[nt], aa0, aa1, aa2, aa3, b0, b1);
                mma_tf32(csB[nt], ba0, ba1, ba2, ba3, b0, b1);
            }
        }

        // ---- max-free softmax: P kept raw; l sums the mma-truncated bits ----
        unsigned long long mm =
            (unsigned long long)sMask[t * 2] |
            ((unsigned long long)sMask[t * 2 + 1] << 32);

        #pragma unroll
        for (int nt = 0; nt < 8; nt++) {
            int c0 = nt * 8 + 2 * q, c1 = c0 + 1;
            bool k0 = (mm >> c0) & 1ull, k1 = (mm >> c1) & 1ull;
            float pa0 = fexp2(k0 ? csA[nt][0] * SC2 : NEGV2);
            float pa1 = fexp2(k1 ? csA[nt][1] * SC2 : NEGV2);
            float pa2 = fexp2(k0 ? csA[nt][2] * SC2 : NEGV2);
            float pa3 = fexp2(k1 ? csA[nt][3] * SC2 : NEGV2);
            float pb0 = fexp2(k0 ? csB[nt][0] * SC2 : NEGV2);
            float pb1 = fexp2(k1 ? csB[nt][1] * SC2 : NEGV2);
            float pb2 = fexp2(k0 ? csB[nt][2] * SC2 : NEGV2);
            float pb3 = fexp2(k1 ? csB[nt][3] * SC2 : NEGV2);
            lpA0 += tr13(pa0) + tr13(pa1);  lpA1 += tr13(pa2) + tr13(pa3);
            lpB0 += tr13(pb0) + tr13(pb1);  lpB1 += tr13(pb2) + tr13(pb3);
            csA[nt][0] = pa0; csA[nt][1] = pa1; csA[nt][2] = pa2; csA[nt][3] = pa3;
            csB[nt][0] = pb0; csB[nt][1] = pb1; csB[nt][2] = pb2; csB[nt][3] = pb3;
        }

        // ---- O += P @ V ----
        #pragma unroll
        for (int ks = 0; ks < 8; ks++) {
            uint32_t aa0 = __float_as_uint(csA[ks][0]);
            uint32_t aa1 = __float_as_uint(csA[ks][2]);
            uint32_t aa2 = __float_as_uint(csA[ks][1]);
            uint32_t aa3 = __float_as_uint(csA[ks][3]);
            uint32_t ba0 = __float_as_uint(csB[ks][0]);
            uint32_t ba1 = __float_as_uint(csB[ks][2]);
            uint32_t ba2 = __float_as_uint(csB[ks][1]);
            uint32_t ba3 = __float_as_uint(csB[ks][3]);
            #pragma unroll
            for (int nt = 0; nt < 8; nt++) {
                float2 B = *(const float2*)(vb + (nt * 8 + gr) * VS_ + ks * 8 + 2 * q);
                uint32_t b0 = __float_as_uint(B.x), b1 = __float_as_uint(B.y);
                mma_tf32(oA[nt], aa0, aa1, aa2, aa3, b0, b1);
                mma_tf32(oB[nt], ba0, ba1, ba2, ba3, b0, b1);
            }
        }

        if (t < 7) {
            CP_WAIT0();
            __syncthreads();
            p ^= 1;
        }
    }

    // ---- epilogue ----
    {
        lpA0 += __shfl_xor_sync(0xffffffffu, lpA0, 1);
        lpA0 += __shfl_xor_sync(0xffffffffu, lpA0, 2);
        lpA1 += __shfl_xor_sync(0xffffffffu, lpA1, 1);
        lpA1 += __shfl_xor_sync(0xffffffffu, lpA1, 2);
        lpB0 += __shfl_xor_sync(0xffffffffu, lpB0, 1);
        lpB0 += __shfl_xor_sync(0xffffffffu, lpB0, 2);
        lpB1 += __shfl_xor_sync(0xffffffffu, lpB1, 1);
        lpB1 += __shfl_xor_sync(0xffffffffu, lpB1, 2);
        float iA0 = 1.0f / lpA0, iA1 = 1.0f / lpA1;
        float iB0 = 1.0f / lpB0, iB1 = 1.0f / lpB1;
        float* dA0 = g_attn + (row0 + rA0) * EE + h * DD;
        float* dA1 = dA0 + 8 * EE;
        float* dB0 = g_attn + (row0 + rB0) * EE + h * DD;
        float* dB1 = dB0 + 8 * EE;
        #pragma unroll
        for (int nt = 0; nt < 8; nt++) {
            int c = nt * 8 + 2 * q;
            *(float2*)(dA0 + c) = make_float2(to_tf32(oA[nt][0] * iA0),
                                              to_tf32(oA[nt][1] * iA0));
            *(float2*)(dA1 + c) = make_float2(to_tf32(oA[nt][2] * iA1),
                                              to_tf32(oA[nt][3] * iA1));
            *(float2*)(dB0 + c) = make_float2(to_tf32(oB[nt][0] * iB0),
                                              to_tf32(oB[nt][1] * iB0));
            *(float2*)(dB1 + c) = make_float2(to_tf32(oB[nt][2] * iB1),
                                              to_tf32(oB[nt][3] * iB1));
        }
    }
}

// ===========================================================================
// Output projection: 256x128 tiles (L2 traffic 128->96MB), 256 threads,
// 8 warps x 32 rows (strips A/B). k-chunk 32, cp.async ping-pong. grid (32,4).
// PDL: W stage 0 issued before grid-sync.
// ===========================================================================
#define OS 40
#define XB_OFF 0
#define WB_OFF (2 * 256 * OS)
#define OUTP_SMEM ((WB_OFF + 2 * 128 * OS) * 4)

__global__ __launch_bounds__(256, 1) void outproj_mma_kernel(
    const float* __restrict__ bo, float* __restrict__ out)
{
    extern __shared__ float sm[];
    const uint32_t smb = smem_u32(sm);

    const int tid = threadIdx.x;
    const int w = tid >> 5, l = tid & 31;
    const int gr = l >> 2, q = l & 3;
    const int rA0 = w * 32 + gr;
    const int rB0 = rA0 + 16;

    const size_t row0 = (size_t)blockIdx.x * 256;
    const int    col0 = blockIdx.y * 128;

    int xr[8];
    #pragma unroll
    for (int j = 0; j < 8; j++) xr[j] = (tid + j * 256) >> 3;
    const int cc = (tid & 7) * 4;

    float accA[16][4], accB[16][4];
    #pragma unroll
    for (int nt = 0; nt < 16; nt++)
        #pragma unroll
        for (int j = 0; j < 4; j++) { accA[nt][j] = 0.f; accB[nt][j] = 0.f; }

    // PDL pre-sync: W stage 0 (depends only on proj's g_WoR)
    {
        uint32_t wd = smb + WB_OFF * 4;
        const float* ws = g_WoR + (size_t)col0 * EE;
        #pragma unroll
        for (int j = 0; j < 4; j++)
            cp_async16(wd + (xr[j] * OS + cc) * 4, ws + (size_t)xr[j] * EE + cc);
        CP_COMMIT();
    }

    cudaGridDependencySynchronize();   // wait for attn's g_attn writes

    {
        uint32_t xd = smb + XB_OFF * 4;
        const float* xs = g_attn + row0 * EE;
        #pragma unroll
        for (int j = 0; j < 8; j++)
            cp_async16(xd + (xr[j] * OS + cc) * 4, xs + (size_t)xr[j] * EE + cc);
        CP_COMMIT();
        CP_WAIT0();
        __syncthreads();
    }

    int p = 0;
    for (int fc = 0; fc < 16; fc++) {
        if (fc < 15) {
            uint32_t xd = smb + (XB_OFF + (p ^ 1) * 256 * OS) * 4;
            uint32_t wd = smb + (WB_OFF + (p ^ 1) * 128 * OS) * 4;
            const float* xs = g_attn + row0 * EE + (fc + 1) * 32;
            const float* ws = g_WoR + (size_t)col0 * EE + (fc + 1) * 32;
            #pragma unroll
            for (int j = 0; j < 8; j++)
                cp_async16(xd + (xr[j] * OS + cc) * 4, xs + (size_t)xr[j] * EE + cc);
            #pragma unroll
            for (int j = 0; j < 4; j++)
                cp_async16(wd + (xr[j] * OS + cc) * 4, ws + (size_t)xr[j] * EE + cc);
            CP_COMMIT();
        }

        const float* sX = sm + XB_OFF + p * 256 * OS;
        const float* sW = sm + WB_OFF + p * 128 * OS;

        #pragma unroll
        for (int ks = 0; ks < 4; ks++) {
            float2 A02 = *(const float2*)(sX + rA0 * OS + ks * 8 + 2 * q);
            float2 A13 = *(const float2*)(sX + (rA0 + 8) * OS + ks * 8 + 2 * q);
            float2 C02 = *(const float2*)(sX + rB0 * OS + ks * 8 + 2 * q);
            float2 C13 = *(const float2*)(sX + (rB0 + 8) * OS + ks * 8 + 2 * q);
            uint32_t aa0 = __float_as_uint(A02.x), aa2 = __float_as_uint(A02.y);
            uint32_t aa1 = __float_as_uint(A13.x), aa3 = __float_as_uint(A13.y);
            uint32_t ba0 = __float_as_uint(C02.x), ba2 = __float_as_uint(C02.y);
            uint32_t ba1 = __float_as_uint(C13.x), ba3 = __float_as_uint(C13.y);
            #pragma unroll
            for (int nt = 0; nt < 16; nt++) {
                float2 B = *(const float2*)(sW + (nt * 8 + gr) * OS + ks * 8 + 2 * q);
                uint32_t b0 = __float_as_uint(B.x), b1 = __float_as_uint(B.y);
                mma_tf32(accA[nt], aa0, aa1, aa2, aa3, b0, b1);
                mma_tf32(accB[nt], ba0, ba1, ba2, ba3, b0, b1);
            }
        }

        if (fc < 15) {
            CP_WAIT0();
            __syncthreads();
            p ^= 1;
        }
    }

    float* dA0 = out + (row0 + rA0) * EE + col0;
    float* dA1 = dA0 + 8 * EE;
    float* dB0 = out + (row0 + rB0) * EE + col0;
    float* dB1 = dB0 + 8 * EE;
    #pragma unroll
    for (int nt = 0; nt < 16; nt++) {
        int c = nt * 8 + 2 * q;
        float b0 = bo[col0 + c], b1 = bo[col0 + c + 1];
        *(float2*)(dA0 + c) = make_float2(accA[nt][0] + b0, accA[nt][1] + b1);
        *(float2*)(dA1 + c) = make_float2(accA[nt][2] + b0, accA[nt][3] + b1);
        *(float2*)(dB0 + c) = make_float2(accB[nt][0] + b0, accB[nt][1] + b1);
        *(float2*)(dB1 + c) = make_float2(accB[nt][2] + b0, accB[nt][3] + b1);
    }
}

// ===========================================================================
extern "C" void kernel_launch(void* const* d_in, const int* in_sizes, int n_in,
                              void* d_out, int out_size)
{
    const float* values = (const float*)d_in[0];
    const float* keys   = (const float*)d_in[1];
    const float* query  = (const float*)d_in[2];
    const int*   mask   = (const int*)  d_in[3];
    const float* Wv     = (const float*)d_in[4];
    const float* Wk     = (const float*)d_in[5];
    const float* Wq     = (const float*)d_in[6];
    const float* Wo     = (const float*)d_in[7];
    const float* bo     = (const float*)d_in[8];
    float* out          = (float*)d_out;

    cudaFuncSetAttribute(proj_all_kernel,
                         cudaFuncAttributeMaxDynamicSharedMemorySize, PROJ_SMEM);
    cudaFuncSetAttribute(attn_mma_kernel,
                         cudaFuncAttributeMaxDynamicSharedMemorySize, ATTN_SMEM);
    cudaFuncSetAttribute(outproj_mma_kernel,
                         cudaFuncAttributeMaxDynamicSharedMemorySize, OUTP_SMEM);

    // K/V projections + Wo prep (all cp.async staging)
    proj_all_kernel<<<dim3(72, HH), 128, PROJ_SMEM>>>(keys, Wk, values, Wv, Wo);

    // Flash attention (PDL; prologue overlaps proj; early trigger for outproj)
    {
        cudaLaunchConfig_t cfg = {};
        cfg.gridDim = dim3(64, HH);
        cfg.blockDim = dim3(128);
        cfg.dynamicSmemBytes = ATTN_SMEM;
        cfg.stream = 0;
        cudaLaunchAttribute at[1];
        at[0].id = cudaLaunchAttributeProgrammaticStreamSerialization;
        at[0].val.programmaticStreamSerializationAllowed = 1;
        cfg.attrs = at;
        cfg.numAttrs = 1;
        cudaLaunchKernelEx(&cfg, attn_mma_kernel, query, Wq, mask);
    }

    // Output projection (PDL: W staging overlaps attn tail)
    {
        cudaLaunchConfig_t cfg = {};
        cfg.gridDim = dim3(32, 4);
        cfg.blockDim = dim3(256);
        cfg.dynamicSmemBytes = OUTP_SMEM;
        cfg.stream = 0;
        cudaLaunchAttribute at[1];
        at[0].id = cudaLaunchAttributeProgrammaticStreamSerialization;
        at[0].val.programmaticStreamSerializationAllowed = 1;
        cfg.attrs = at;
        cfg.numAttrs = 1;
        cudaLaunchKernelEx(&cfg, outproj_mma_kernel, bo, out);
    }
}

// round 16
// speedup vs baseline: 1.2611x; 1.1183x over previous
#include <cuda_runtime.h>
#include <cuda_bf16.h>
#include <math.h>
#include <stdint.h>

#define NB 4
#define KL 512
#define QL 32
#define SS 64
#define EE 512
#define HH 8
#define DD 64

// Scratch (allocation-free). K bf16 (logit path); V/attn/Wo fp32 (value path).
__device__ __nv_bfloat16 g_kproj[NB * KL * EE];      // 2 MB [row][e]
__device__ float g_vT   [NB * HH * DD * KL];          // 4 MB [nh][d][key] tf32
__device__ float g_attn [NB * QL * SS * EE];          // 16 MB (rna tf32)
__device__ float g_WoR  [EE * EE];                    // 1 MB  (rna tf32)

// ===========================================================================
// helpers
// ===========================================================================
__device__ __forceinline__ float to_tf32(float x) {
    uint32_t o;
    asm("cvt.rna.tf32.f32 %0, %1;" : "=r"(o) : "f"(x));
    return __uint_as_float(o);
}

// truncation to tf32 bits — matches what HMMA reads from a raw fp32
__device__ __forceinline__ float tr13(float x) {
    return __uint_as_float(__float_as_uint(x) & 0xffffe000u);
}

__device__ __forceinline__ uint32_t packbf(float lo, float hi) {
    uint32_t r;
    asm("cvt.rn.bf16x2.f32 %0, %1, %2;" : "=r"(r) : "f"(hi), "f"(lo));
    return r;
}

__device__ __forceinline__ float fexp2(float x) {
    float y;
    asm("ex2.approx.ftz.f32 %0, %1;" : "=f"(y) : "f"(x));
    return y;
}

__device__ __forceinline__ uint32_t smem_u32(const void* p) {
    uint32_t a;
    asm("{ .reg .u64 t; cvta.to.shared.u64 t, %1; cvt.u32.u64 %0, t; }"
        : "=r"(a) : "l"(p));
    return a;
}

__device__ __forceinline__ void cp_async16(uint32_t dst, const void* src) {
    asm volatile("cp.async.cg.shared.global [%0], [%1], 16;"
                 :: "r"(dst), "l"(src) : "memory");
}
#define CP_COMMIT() asm volatile("cp.async.commit_group;" ::: "memory")
#define CP_WAIT0()  asm volatile("cp.async.wait_group 0;" ::: "memory")

__device__ __forceinline__ void mma_tf32(float c[4],
                                         uint32_t a0, uint32_t a1,
                                         uint32_t a2, uint32_t a3,
                                         uint32_t b0, uint32_t b1) {
    asm volatile(
        "mma.sync.aligned.m16n8k8.row.col.f32.tf32.tf32.f32 "
        "{%0,%1,%2,%3}, {%4,%5,%6,%7}, {%8,%9}, {%0,%1,%2,%3};"
        : "+f"(c[0]), "+f"(c[1]), "+f"(c[2]), "+f"(c[3])
        : "r"(a0), "r"(a1), "r"(a2), "r"(a3), "r"(b0), "r"(b1));
}

__device__ __forceinline__ void mma_bf16(float c[4],
                                         uint32_t a0, uint32_t a1,
                                         uint32_t a2, uint32_t a3,
                                         uint32_t b0, uint32_t b1) {
    asm volatile(
        "mma.sync.aligned.m16n8k16.row.col.f32.bf16.bf16.f32 "
        "{%0,%1,%2,%3}, {%4,%5,%6,%7}, {%8,%9}, {%0,%1,%2,%3};"
        : "+f"(c[0]), "+f"(c[1]), "+f"(c[2]), "+f"(c[3])
        : "r"(a0), "r"(a1), "r"(a2), "r"(a3), "r"(b0), "r"(b1));
}

// ===========================================================================
// K (bf16 out) / V (tf32 out, transposed) projections + Wo rna copy.
// grid = (72, HH): x<32 -> K, x<64 -> V, x>=64 -> Wo prep. 128 threads.
// ===========================================================================
#define PJ_S 68
#define PROJ_SMEM ((2 * 64 * PJ_S) * 4)

__global__ __launch_bounds__(128) void proj_all_kernel(
    const float* __restrict__ keys,   const float* __restrict__ Wk,
    const float* __restrict__ values, const float* __restrict__ Wv,
    const float* __restrict__ Wo)
{
    extern __shared__ float sm[];
    const uint32_t smb = smem_u32(sm);

    cudaTriggerProgrammaticLaunchCompletion();

    const int tid = threadIdx.x;
    const int h = blockIdx.y;
    const int bx = blockIdx.x;

    if (bx >= 64) {
        const int baseg = ((bx - 64) * 8 + h) * 512;
        #pragma unroll
        for (int j = 0; j < 4; j++) {
            int gid = baseg + tid + j * 128;
            int r = gid >> 6, grp = gid & 63;
            const float* src = Wo + (size_t)r * EE + grp * 8;
            float4 a = *(const float4*)(src);
            float4 b = *(const float4*)(src + 4);
            float* dst = g_WoR + (size_t)r * EE + grp * 8;
            *(float4*)(dst)     = make_float4(to_tf32(a.x), to_tf32(a.y),
                                              to_tf32(a.z), to_tf32(a.w));
            *(float4*)(dst + 4) = make_float4(to_tf32(b.x), to_tf32(b.y),
                                              to_tf32(b.z), to_tf32(b.w));
        }
        return;
    }

    const int w = tid >> 5, l = tid & 31;
    const int gr = l >> 2, q = l & 3;
    const int rw = w * 16;

    const int mode = (bx >= 32);
    const float* in = mode ? values : keys;
    const float* W  = mode ? Wv : Wk;
    const int row0 = (bx & 31) * 64;

    // cp.async raw inputs (truncated tf32 in mma)
    #pragma unroll
    for (int j = 0; j < 8; j++) {
        int c = tid + j * 128;
        int r = c >> 4, col = (c & 15) * 4;
        cp_async16(smb + (uint32_t)(r * PJ_S + col) * 4,
                   in + (size_t)(row0 + r) * EE + h * DD + col);
    }
    #pragma unroll
    for (int j = 0; j < 8; j++) {
        int c = tid + j * 128;
        int r = c >> 4, col = (c & 15) * 4;
        cp_async16(smb + (uint32_t)(64 * PJ_S + r * PJ_S + col) * 4,
                   W + (size_t)r * 64 + col);
    }
    CP_COMMIT();
    CP_WAIT0();
    __syncthreads();

    const float* sIn = sm;
    const float* sW  = sm + 64 * PJ_S;

    float acc[8][4];
    #pragma unroll
    for (int nt = 0; nt < 8; nt++)
        #pragma unroll
        for (int j = 0; j < 4; j++) acc[nt][j] = 0.f;

    #pragma unroll
    for (int ks = 0; ks < 8; ks++) {
        float2 A02 = *(const float2*)(sIn + (rw + gr) * PJ_S + ks * 8 + 2 * q);
        float2 A13 = *(const float2*)(sIn + (rw + gr + 8) * PJ_S + ks * 8 + 2 * q);
        uint32_t a0 = __float_as_uint(A02.x), a2 = __float_as_uint(A02.y);
        uint32_t a1 = __float_as_uint(A13.x), a3 = __float_as_uint(A13.y);
        #pragma unroll
        for (int nt = 0; nt < 8; nt++) {
            float2 B = *(const float2*)(sW + (nt * 8 + gr) * PJ_S + ks * 8 + 2 * q);
            mma_tf32(acc[nt], a0, a1, a2, a3,
                     __float_as_uint(B.x), __float_as_uint(B.y));
        }
    }
    __syncthreads();

    if (mode == 0) {
        // K: stage fp32, convert to bf16 on coalesced copy-out
        #pragma unroll
        for (int nt = 0; nt < 8; nt++) {
            *(float2*)(sm + (rw + gr) * PJ_S + nt * 8 + 2 * q) =
                make_float2(acc[nt][0], acc[nt][1]);
            *(float2*)(sm + (rw + gr + 8) * PJ_S + nt * 8 + 2 * q) =
                make_float2(acc[nt][2], acc[nt][3]);
        }
        __syncthreads();
        #pragma unroll
        for (int j = 0; j < 4; j++) {
            int i = tid + j * 128;           // 512 chunks: 64 rows x 8
            int r = i >> 3, c8 = i & 7;
            const float* s = sm + r * PJ_S + c8 * 8;
            float4 a = *(const float4*)(s);
            float4 b = *(const float4*)(s + 4);
            uint4 o;
            o.x = packbf(a.x, a.y); o.y = packbf(a.z, a.w);
            o.z = packbf(b.x, b.y); o.w = packbf(b.z, b.w);
            *(uint4*)(g_kproj + (size_t)(row0 + r) * EE + h * DD + c8 * 8) = o;
        }
    } else {
        // V: transpose to [d][key] via [64][132] staging, tf32 out (fp32)
        const int n = row0 >> 9;
        const int keyb = row0 & (KL - 1);
        const int kA = rw + gr, kB = rw + gr + 8;
        #pragma unroll
        for (int nt = 0; nt < 8; nt++) {
            int c0 = nt * 8 + 2 * q, c1 = c0 + 1;
            sm[c0 * 132 + kA] = to_tf32(acc[nt][0]);
            sm[c1 * 132 + kA] = to_tf32(acc[nt][1]);
            sm[c0 * 132 + kB] = to_tf32(acc[nt][2]);
            sm[c1 * 132 + kB] = to_tf32(acc[nt][3]);
        }
        __syncthreads();
        float* base = g_vT + (size_t)(n * HH + h) * DD * KL + keyb;
        #pragma unroll
        for (int j = 0; j < 8; j++) {
            int i = tid + j * 128;
            int d = i >> 4, c4 = i & 15;
            *(float4*)(base + (size_t)d * KL + c4 * 4) =
                *(const float4*)(sm + d * 132 + c4 * 4);
        }
    }
}

// ===========================================================================
// Flash attention: bf16 m16n8k16 for QK^T, tf32 m16n8k8 for P@V.
// 4 warps x 32 q-rows, 128 threads, 2 CTAs/SM, PDL.
// ===========================================================================
// smem byte offsets
#define KBB   0                      // 2 x 64 x 144 (bf16)      = 18432
#define KTILE 9216
#define VBB   18432                  // 2 x 64 x 288 (fp32 s72)  = 36864
#define VTILE 18432
#define WQB   55296                  // 64 x 288                 = 18432
#define QQB   73728                  // 128 x 288                = 36864
#define MSKB  110592                 // 64
#define ATTN_SMEM 110656
#define KVS 144

__global__ __launch_bounds__(128, 2) void attn_mma_kernel(
    const float* __restrict__ query, const float* __restrict__ Wq,
    const int* __restrict__ mask)
{
    extern __shared__ __align__(16) char smc[];
    float* smf = (float*)smc;
    uint32_t* sMask = (uint32_t*)(smc + MSKB);
    const uint32_t smb = smem_u32(smc);

    cudaTriggerProgrammaticLaunchCompletion();

    const int tid = threadIdx.x;
    const int w = tid >> 5, l = tid & 31;
    const int gr = l >> 2, q = l & 3;
    const int rA0 = w * 32 + gr;
    const int rB0 = rA0 + 16;

    const int h  = blockIdx.y;
    const int bx = blockIdx.x;
    const int n  = bx >> 4;
    const size_t row0 = (size_t)bx * 128;

    const __nv_bfloat16* kbase = g_kproj + (size_t)(n * KL) * EE + h * DD;
    const float* vbase = g_vT + (size_t)(n * HH + h) * DD * KL;

    if (tid < 16) {
        uint32_t wv = 0;
        const int* mp = mask + n * KL + tid * 32;
        #pragma unroll
        for (int b = 0; b < 32; b++) wv |= (mp[b] ? (1u << b) : 0u);
        sMask[tid] = wv;
    }

    // ---- PDL pre-sync: Q + Wq staging (fp32, kernel inputs only) ----
    #pragma unroll
    for (int j = 0; j < 16; j++) {
        int c = tid + j * 128;
        int r = c >> 4, col = (c & 15) * 4;
        cp_async16(smb + QQB + (uint32_t)(r * 288 + col * 4),
                   query + (row0 + r) * EE + h * DD + col);
    }
    #pragma unroll
    for (int j = 0; j < 8; j++) {
        int c = tid + j * 128;
        int r = c >> 4, col = (c & 15) * 4;
        cp_async16(smb + WQB + (uint32_t)(r * 288 + col * 4),
                   Wq + (size_t)r * 64 + col);
    }
    CP_COMMIT();
    CP_WAIT0();
    __syncthreads();

    // ---- fused Q projection (tf32), pack C-frags into bf16 k16 A-frags ----
    uint32_t qbA[4][4], qbB[4][4];
    {
        float qaccA[8][4], qaccB[8][4];
        #pragma unroll
        for (int nt = 0; nt < 8; nt++)
            #pragma unroll
            for (int j = 0; j < 4; j++) { qaccA[nt][j] = 0.f; qaccB[nt][j] = 0.f; }

        const float* qrowA = smf + QQB / 4 + (w * 32 + gr) * 72;
        const float* qrowB = qrowA + 16 * 72;
        const float* wqb   = smf + WQB / 4;
        #pragma unroll
        for (int ks = 0; ks < 8; ks++) {
            float2 A02 = *(const float2*)(qrowA + ks * 8 + 2 * q);
            float2 A13 = *(const float2*)(qrowA + 8 * 72 + ks * 8 + 2 * q);
            float2 C02 = *(const float2*)(qrowB + ks * 8 + 2 * q);
            float2 C13 = *(const float2*)(qrowB + 8 * 72 + ks * 8 + 2 * q);
            uint32_t aa0 = __float_as_uint(A02.x), aa2 = __float_as_uint(A02.y);
            uint32_t aa1 = __float_as_uint(A13.x), aa3 = __float_as_uint(A13.y);
            uint32_t ba0 = __float_as_uint(C02.x), ba2 = __float_as_uint(C02.y);
            uint32_t ba1 = __float_as_uint(C13.x), ba3 = __float_as_uint(C13.y);
            #pragma unroll
            for (int nt = 0; nt < 8; nt++) {
                float2 B = *(const float2*)(wqb + (nt * 8 + gr) * 72 + ks * 8 + 2 * q);
                uint32_t b0 = __float_as_uint(B.x), b1 = __float_as_uint(B.y);
                mma_tf32(qaccA[nt], aa0, aa1, aa2, aa3, b0, b1);
                mma_tf32(qaccB[nt], ba0, ba1, ba2, ba3, b0, b1);
            }
        }
        #pragma unroll
        for (int ks = 0; ks < 4; ks++) {
            qbA[ks][0] = packbf(qaccA[2*ks][0],   qaccA[2*ks][1]);
            qbA[ks][1] = packbf(qaccA[2*ks][2],   qaccA[2*ks][3]);
            qbA[ks][2] = packbf(qaccA[2*ks+1][0], qaccA[2*ks+1][1]);
            qbA[ks][3] = packbf(qaccA[2*ks+1][2], qaccA[2*ks+1][3]);
            qbB[ks][0] = packbf(qaccB[2*ks][0],   qaccB[2*ks][1]);
            qbB[ks][1] = packbf(qaccB[2*ks][2],   qaccB[2*ks][3]);
            qbB[ks][2] = packbf(qaccB[2*ks+1][0], qaccB[2*ks+1][1]);
            qbB[ks][3] = packbf(qaccB[2*ks+1][2], qaccB[2*ks+1][3]);
        }
    }
    __syncthreads();

    // ---- wait for proj writes; stream K (bf16) + V (fp32) tile 0 ----
    cudaGridDependencySynchronize();
    {
        #pragma unroll
        for (int j = 0; j < 4; j++) {
            int c = tid + j * 128;           // 512 chunks (64 rows x 8)
            int r = c >> 3, e8 = (c & 7) * 8;
            cp_async16(smb + KBB + (uint32_t)(r * KVS + e8 * 2),
                       kbase + (size_t)r * EE + e8);
        }
        #pragma unroll
        for (int j = 0; j < 8; j++) {
            int c = tid + j * 128;           // 1024 chunks (64 rows x 16)
            int r = c >> 4, col = (c & 15) * 4;
            cp_async16(smb + VBB + (uint32_t)(r * 288 + col * 4),
                       vbase + (size_t)r * KL + col);
        }
        CP_COMMIT();
    }
    CP_WAIT0();
    __syncthreads();

    const float SC2   = 0.04419417382415922f * 1.4426950408889634f;
    const float NEGV2 = -1e20f * (0.04419417382415922f * 1.4426950408889634f);

    float oA[8][4], oB[8][4];
    #pragma unroll
    for (int nt = 0; nt < 8; nt++)
        #pragma unroll
        for (int j = 0; j < 4; j++) { oA[nt][j] = 0.f; oB[nt][j] = 0.f; }
    float lpA0 = 0.f, lpA1 = 0.f, lpB0 = 0.f, lpB1 = 0.f;

    int p = 0;
    for (int t = 0; t < 8; t++) {
        if (t < 7) {
            const __nv_bfloat16* ks = kbase + (size_t)(t + 1) * 64 * EE;
            const float* vs = vbase + (t + 1) * 64;
            #pragma unroll
            for (int j = 0; j < 4; j++) {
                int c = tid + j * 128;
                int r = c >> 3, e8 = (c & 7) * 8;
                cp_async16(smb + KBB + (uint32_t)((p ^ 1) * KTILE + r * KVS + e8 * 2),
                           ks + (size_t)r * EE + e8);
            }
            #pragma unroll
            for (int j = 0; j < 8; j++) {
                int c = tid + j * 128;
                int r = c >> 4, col = (c & 15) * 4;
                cp_async16(smb + VBB + (uint32_t)((p ^ 1) * VTILE + r * 288 + col * 4),
                           vs + (size_t)r * KL + col);
            }
            CP_COMMIT();
        }

        const char*  kb = smc + KBB + p * KTILE;
        const float* vb = (const float*)(smc + VBB + p * VTILE);

        // ---- S = Q @ K^T (bf16 k16; B shared across strips) ----
        float csA[8][4], csB[8][4];
        #pragma unroll
        for (int nt = 0; nt < 8; nt++)
            #pragma unroll
            for (int j = 0; j < 4; j++) { csA[nt][j] = 0.f; csB[nt][j] = 0.f; }

        #pragma unroll
        for (int ks = 0; ks < 4; ks++) {
            uint32_t aa0 = qbA[ks][0], aa1 = qbA[ks][1],
                     aa2 = qbA[ks][2], aa3 = qbA[ks][3];
            uint32_t ba0 = qbB[ks][0], ba1 = qbB[ks][1],
                     ba2 = qbB[ks][2], ba3 = qbB[ks][3];
            #pragma unroll
            for (int nt = 0; nt < 8; nt++) {
                const char* bp = kb + (nt * 8 + gr) * KVS + (ks * 16 + 2 * q) * 2;
                uint32_t b0 = *(const uint32_t*)(bp);
                uint32_t b1 = *(const uint32_t*)(bp + 16);
                mma_bf16(csA[nt], aa0, aa1, aa2, aa3, b0, b1);
                mma_bf16(csB[nt], ba0, ba1, ba2, ba3, b0, b1);
            }
        }

        // ---- max-free softmax: P kept raw fp32; l sums truncated bits ----
        unsigned long long mm =
            (unsigned long long)sMask[t * 2] |
            ((unsigned long long)sMask[t * 2 + 1] << 32);

        #pragma unroll
        for (int nt = 0; nt < 8; nt++) {
            int c0 = nt * 8 + 2 * q, c1 = c0 + 1;
            bool k0 = (mm >> c0) & 1ull, k1 = (mm >> c1) & 1ull;
            float pa0 = fexp2(k0 ? csA[nt][0] * SC2 : NEGV2);
            float pa1 = fexp2(k1 ? csA[nt][1] * SC2 : NEGV2);
            float pa2 = fexp2(k0 ? csA[nt][2] * SC2 : NEGV2);
            float pa3 = fexp2(k1 ? csA[nt][3] * SC2 : NEGV2);
            float pb0 = fexp2(k0 ? csB[nt][0] * SC2 : NEGV2);
            float pb1 = fexp2(k1 ? csB[nt][1] * SC2 : NEGV2);
            float pb2 = fexp2(k0 ? csB[nt][2] * SC2 : NEGV2);
            float pb3 = fexp2(k1 ? csB[nt][3] * SC2 : NEGV2);
            lpA0 += tr13(pa0) + tr13(pa1);  lpA1 += tr13(pa2) + tr13(pa3);
            lpB0 += tr13(pb0) + tr13(pb1);  lpB1 += tr13(pb2) + tr13(pb3);
            csA[nt][0] = pa0; csA[nt][1] = pa1; csA[nt][2] = pa2; csA[nt][3] = pa3;
            csB[nt][0] = pb0; csB[nt][1] = pb1; csB[nt][2] = pb2; csB[nt][3] = pb3;
        }

        // ---- O += P @ V (tf32 k8, value path) ----
        #pragma unroll
        for (int ks = 0; ks < 8; ks++) {
            uint32_t aa0 = __float_as_uint(csA[ks][0]);
            uint32_t aa1 = __float_as_uint(csA[ks][2]);
            uint32_t aa2 = __float_as_uint(csA[ks][1]);
            uint32_t aa3 = __float_as_uint(csA[ks][3]);
            uint32_t ba0 = __float_as_uint(csB[ks][0]);
            uint32_t ba1 = __float_as_uint(csB[ks][2]);
            uint32_t ba2 = __float_as_uint(csB[ks][1]);
            uint32_t ba3 = __float_as_uint(csB[ks][3]);
            #pragma unroll
            for (int nt = 0; nt < 8; nt++) {
                float2 B = *(const float2*)(vb + (nt * 8 + gr) * 72 + ks * 8 + 2 * q);
                uint32_t b0 = __float_as_uint(B.x), b1 = __float_as_uint(B.y);
                mma_tf32(oA[nt], aa0, aa1, aa2, aa3, b0, b1);
                mma_tf32(oB[nt], ba0, ba1, ba2, ba3, b0, b1);
            }
        }

        if (t < 7) {
            CP_WAIT0();
            __syncthreads();
            p ^= 1;
        }
    }

    // ---- epilogue ----
    {
        lpA0 += __shfl_xor_sync(0xffffffffu, lpA0, 1);
        lpA0 += __shfl_xor_sync(0xffffffffu, lpA0, 2);
        lpA1 += __shfl_xor_sync(0xffffffffu, lpA1, 1);
        lpA1 += __shfl_xor_sync(0xffffffffu, lpA1, 2);
        lpB0 += __shfl_xor_sync(0xffffffffu, lpB0, 1);
        lpB0 += __shfl_xor_sync(0xffffffffu, lpB0, 2);
        lpB1 += __shfl_xor_sync(0xffffffffu, lpB1, 1);
        lpB1 += __shfl_xor_sync(0xffffffffu, lpB1, 2);
        float iA0 = 1.0f / lpA0, iA1 = 1.0f / lpA1;
        float iB0 = 1.0f / lpB0, iB1 = 1.0f / lpB1;
        float* dA0 = g_attn + (row0 + rA0) * EE + h * DD;
        float* dA1 = dA0 + 8 * EE;
        float* dB0 = g_attn + (row0 + rB0) * EE + h * DD;
        float* dB1 = dB0 + 8 * EE;
        #pragma unroll
        for (int nt = 0; nt < 8; nt++) {
            int c = nt * 8 + 2 * q;
            *(float2*)(dA0 + c) = make_float2(to_tf32(oA[nt][0] * iA0),
                                              to_tf32(oA[nt][1] * iA0));
            *(float2*)(dA1 + c) = make_float2(to_tf32(oA[nt][2] * iA1),
                                              to_tf32(oA[nt][3] * iA1));
            *(float2*)(dB0 + c) = make_float2(to_tf32(oB[nt][0] * iB0),
                                              to_tf32(oB[nt][1] * iB0));
            *(float2*)(dB1 + c) = make_float2(to_tf32(oB[nt][2] * iB1),
                                              to_tf32(oB[nt][3] * iB1));
        }
    }
}

// ===========================================================================
// Output projection (tf32): 256x128 tiles, grid (32,4), 256 threads, PDL.
// ===========================================================================
#define OS 40
#define XB_OFF 0
#define WB_OFF (2 * 256 * OS)
#define OUTP_SMEM ((WB_OFF + 2 * 128 * OS) * 4)

__global__ __launch_bounds__(256, 1) void outproj_mma_kernel(
    const float* __restrict__ bo, float* __restrict__ out)
{
    extern __shared__ float sm[];
    const uint32_t smb = smem_u32(sm);

    const int tid = threadIdx.x;
    const int w = tid >> 5, l = tid & 31;
    const int gr = l >> 2, q = l & 3;
    const int rA0 = w * 32 + gr;
    const int rB0 = rA0 + 16;

    const size_t row0 = (size_t)blockIdx.x * 256;
    const int    col0 = blockIdx.y * 128;

    int xr[8];
    #pragma unroll
    for (int j = 0; j < 8; j++) xr[j] = (tid + j * 256) >> 3;
    const int cc = (tid & 7) * 4;

    float accA[16][4], accB[16][4];
    #pragma unroll
    for (int nt = 0; nt < 16; nt++)
        #pragma unroll
        for (int j = 0; j < 4; j++) { accA[nt][j] = 0.f; accB[nt][j] = 0.f; }

    // PDL pre-sync: W stage 0 (depends only on proj's g_WoR)
    {
        uint32_t wd = smb + WB_OFF * 4;
        const float* ws = g_WoR + (size_t)col0 * EE;
        #pragma unroll
        for (int j = 0; j < 4; j++)
            cp_async16(wd + (xr[j] * OS + cc) * 4, ws + (size_t)xr[j] * EE + cc);
        CP_COMMIT();
    }

    cudaGridDependencySynchronize();

    {
        uint32_t xd = smb + XB_OFF * 4;
        const float* xs = g_attn + row0 * EE;
        #pragma unroll
        for (int j = 0; j < 8; j++)
            cp_async16(xd + (xr[j] * OS + cc) * 4, xs + (size_t)xr[j] * EE + cc);
        CP_COMMIT();
        CP_WAIT0();
        __syncthreads();
    }

    int p = 0;
    for (int fc = 0; fc < 16; fc++) {
        if (fc < 15) {
            uint32_t xd = smb + (XB_OFF + (p ^ 1) * 256 * OS) * 4;
            uint32_t wd = smb + (WB_OFF + (p ^ 1) * 128 * OS) * 4;
            const float* xs = g_attn + row0 * EE + (fc + 1) * 32;
            const float* ws = g_WoR + (size_t)col0 * EE + (fc + 1) * 32;
            #pragma unroll
            for (int j = 0; j < 8; j++)
                cp_async16(xd + (xr[j] * OS + cc) * 4, xs + (size_t)xr[j] * EE + cc);
            #pragma unroll
            for (int j = 0; j < 4; j++)
                cp_async16(wd + (xr[j] * OS + cc) * 4, ws + (size_t)xr[j] * EE + cc);
            CP_COMMIT();
        }

        const float* sX = sm + XB_OFF + p * 256 * OS;
        const float* sW = sm + WB_OFF + p * 128 * OS;

        #pragma unroll
        for (int ks = 0; ks < 4; ks++) {
            float2 A02 = *(const float2*)(sX + rA0 * OS + ks * 8 + 2 * q);
            float2 A13 = *(const float2*)(sX + (rA0 + 8) * OS + ks * 8 + 2 * q);
            float2 C02 = *(const float2*)(sX + rB0 * OS + ks * 8 + 2 * q);
            float2 C13 = *(const float2*)(sX + (rB0 + 8) * OS + ks * 8 + 2 * q);
            uint32_t aa0 = __float_as_uint(A02.x), aa2 = __float_as_uint(A02.y);
            uint32_t aa1 = __float_as_uint(A13.x), aa3 = __float_as_uint(A13.y);
            uint32_t ba0 = __float_as_uint(C02.x), ba2 = __float_as_uint(C02.y);
            uint32_t ba1 = __float_as_uint(C13.x), ba3 = __float_as_uint(C13.y);
            #pragma unroll
            for (int nt = 0; nt < 16; nt++) {
                float2 B = *(const float2*)(sW + (nt * 8 + gr) * OS + ks * 8 + 2 * q);
                uint32_t b0 = __float_as_uint(B.x), b1 = __float_as_uint(B.y);
                mma_tf32(accA[nt], aa0, aa1, aa2, aa3, b0, b1);
                mma_tf32(accB[nt], ba0, ba1, ba2, ba3, b0, b1);
            }
        }

        if (fc < 15) {
            CP_WAIT0();
            __syncthreads();
            p ^= 1;
        }
    }

    float* dA0 = out + (row0 + rA0) * EE + col0;
    float* dA1 = dA0 + 8 * EE;
    float* dB0 = out + (row0 + rB0) * EE + col0;
    float* dB1 = dB0 + 8 * EE;
    #pragma unroll
    for (int nt = 0; nt < 16; nt++) {
        int c = nt * 8 + 2 * q;
        float b0 = bo[col0 + c], b1 = bo[col0 + c + 1];
        *(float2*)(dA0 + c) = make_float2(accA[nt][0] + b0, accA[nt][1] + b1);
        *(float2*)(dA1 + c) = make_float2(accA[nt][2] + b0, accA[nt][3] + b1);
        *(float2*)(dB0 + c) = make_float2(accB[nt][0] + b0, accB[nt][1] + b1);
        *(float2*)(dB1 + c) = make_float2(accB[nt][2] + b0, accB[nt][3] + b1);
    }
}

// ===========================================================================
extern "C" void kernel_launch(void* const* d_in, const int* in_sizes, int n_in,
                              void* d_out, int out_size)
{
    const float* values = (const float*)d_in[0];
    const float* keys   = (const float*)d_in[1];
    const float* query  = (const float*)d_in[2];
    const int*   mask   = (const int*)  d_in[3];
    const float* Wv     = (const float*)d_in[4];
    const float* Wk     = (const float*)d_in[5];
    const float* Wq     = (const float*)d_in[6];
    const float* Wo     = (const float*)d_in[7];
    const float* bo     = (const float*)d_in[8];
    float* out          = (float*)d_out;

    cudaFuncSetAttribute(proj_all_kernel,
                         cudaFuncAttributeMaxDynamicSharedMemorySize, PROJ_SMEM);
    cudaFuncSetAttribute(attn_mma_kernel,
                         cudaFuncAttributeMaxDynamicSharedMemorySize, ATTN_SMEM);
    cudaFuncSetAttribute(outproj_mma_kernel,
                         cudaFuncAttributeMaxDynamicSharedMemorySize, OUTP_SMEM);

    // K (bf16) / V (tf32) projections + Wo prep
    proj_all_kernel<<<dim3(72, HH), 128, PROJ_SMEM>>>(keys, Wk, values, Wv, Wo);

    // Flash attention (bf16 QK, tf32 PV, PDL)
    {
        cudaLaunchConfig_t cfg = {};
        cfg.gridDim = dim3(64, HH);
        cfg.blockDim = dim3(128);
        cfg.dynamicSmemBytes = ATTN_SMEM;
        cfg.stream = 0;
        cudaLaunchAttribute at[1];
        at[0].id = cudaLaunchAttributeProgrammaticStreamSerialization;
        at[0].val.programmaticStreamSerializationAllowed = 1;
        cfg.attrs = at;
        cfg.numAttrs = 1;
        cudaLaunchKernelEx(&cfg, attn_mma_kernel, query, Wq, mask);
    }

    // Output projection (tf32, PDL)
    {
        cudaLaunchConfig_t cfg = {};
        cfg.gridDim = dim3(32, 4);
        cfg.blockDim = dim3(256);
        cfg.dynamicSmemBytes = OUTP_SMEM;
        cfg.stream = 0;
        cudaLaunchAttribute at[1];
        at[0].id = cudaLaunchAttributeProgrammaticStreamSerialization;
        at[0].val.programmaticStreamSerializationAllowed = 1;
        cfg.attrs = at;
        cfg.numAttrs = 1;
        cudaLaunchKernelEx(&cfg, outproj_mma_kernel, bo, out);
    }
}